// round 8
// baseline (speedup 1.0000x reference)
#include <cuda_runtime.h>
#include <cuda.h>
#include <cstring>

// ---------------------------------------------------------------------------
// Performer (FAVOR+) linear attention, fully fused, fp32 + packed fma.rn.f32x2.
// R7: TMA tile loads (no STS staging, latency pre-issued one sync early),
// out-GEMM split over e-halves (no partial-combine smem round trip).
// One CTA per (b,h). ratio = m^-0.5 cancels through D_inv and is dropped.
// ---------------------------------------------------------------------------

namespace {
constexpr int N_TOK  = 2048;
constexpr int D_DIM  = 64;
constexpr int M_FEAT = 256;
constexpr int NT     = 64;
constexpr int NTILES = N_TOK / NT;         // 32
constexpr int THREADS = 512;
constexpr int BH     = 128;

constexpr int PSLD = 256;
constexpr int KSLD = 64;                   // TMA-compact K/Q tile
constexpr int KPLD = 260;                  // 1040B row stride: 16B-aligned, bank-skewed

// smem layout (float offsets)
constexpr int OFF_P    = 0;                         // Ps[64][256]     16384
constexpr int OFF_KP   = OFF_P   + D_DIM * PSLD;    // kp[64][260]     16640
constexpr int OFF_KS   = OFF_KP  + NT * KPLD;       // Ks[64][64]       4096 (TMA dst)
constexpr int OFF_X    = OFF_KS  + NT * KSLD;       // Vs[64][64] | ctx[256][64] 16384
constexpr int OFF_KCS  = OFF_X   + M_FEAT * D_DIM;  // kcs[256]
constexpr int OFF_DIAG = OFF_KCS + M_FEAT;          // diag[64]
constexpr int OFF_HM   = OFF_DIAG + NT;             // hm[64][2]
constexpr int OFF_HD   = OFF_HM + 2 * NT;           // hd[64][2]
constexpr int OFF_MBAR = OFF_HD + 2 * NT;           // 2 mbarriers (16B)
constexpr int SMEM_FLOATS = OFF_MBAR + 8;
constexpr int SMEM_BYTES  = SMEM_FLOATS * 4;        // ~216 KB

constexpr int TILE_BYTES = NT * D_DIM * 4;          // 16384

constexpr float NRM   = 0.35355339059327373f;       // 64^-0.25
constexpr float DIAGC = 0.0625f;                    // 0.5 * NRM^2
constexpr float EPSF  = 1e-4f;
}

// ---- packed fp32x2 helpers ----
using ull = unsigned long long;

__device__ __forceinline__ ull dup2(float x) {
    ull r; asm("mov.b64 %0, {%1, %1};" : "=l"(r) : "f"(x)); return r;
}
__device__ __forceinline__ void ffma2(ull& d, ull a, ull b) {
    asm("fma.rn.f32x2 %0, %1, %2, %0;" : "+l"(d) : "l"(a), "l"(b));
}
__device__ __forceinline__ float2 unpk(ull v) {
    float2 f; asm("mov.b64 {%0, %1}, %2;" : "=f"(f.x), "=f"(f.y) : "l"(v)); return f;
}

// ---- TMA / mbarrier helpers ----
__device__ __forceinline__ unsigned smem_u32(const void* p) {
    unsigned a;
    asm("{ .reg .u64 t; cvta.to.shared.u64 t, %1; cvt.u32.u64 %0, t; }"
        : "=r"(a) : "l"(p));
    return a;
}
__device__ __forceinline__ void mbar_init(unsigned mbar, unsigned cnt) {
    asm volatile("mbarrier.init.shared.b64 [%0], %1;" :: "r"(mbar), "r"(cnt) : "memory");
}
__device__ __forceinline__ void mbar_expect_tx(unsigned mbar, unsigned bytes) {
    asm volatile("mbarrier.arrive.expect_tx.shared.b64 _, [%0], %1;"
                 :: "r"(mbar), "r"(bytes) : "memory");
}
__device__ __forceinline__ void mbar_wait(unsigned mbar, unsigned parity) {
    asm volatile(
        "{\n\t.reg .pred P1;\n\t"
        "WL_%=:\n\t"
        "mbarrier.try_wait.parity.acquire.cta.shared::cta.b64 P1, [%0], %1, 0x989680;\n\t"
        "@P1 bra.uni WD_%=;\n\t"
        "bra.uni WL_%=;\n\t"
        "WD_%=:\n\t}"
        :: "r"(mbar), "r"(parity) : "memory");
}
__device__ __forceinline__ void tma_load_2d(unsigned dst, const CUtensorMap* tmap,
                                            int x, int y, unsigned mbar) {
    asm volatile(
        "cp.async.bulk.tensor.2d.shared::cta.global.tile.mbarrier::complete_tx::bytes "
        "[%0], [%1, {%2, %3}], [%4];"
        :: "r"(dst), "l"(tmap), "r"(x), "r"(y), "r"(mbar) : "memory");
}

__global__ __launch_bounds__(THREADS, 1)
void fastattn_kernel(const __grid_constant__ CUtensorMap tmQ,
                     const __grid_constant__ CUtensorMap tmK,
                     const __grid_constant__ CUtensorMap tmV,
                     const float* __restrict__ Pg,
                     float* __restrict__ outg_)
{
    extern __shared__ float sm[];
    float* Ps   = sm + OFF_P;
    float* kp   = sm + OFF_KP;
    float* Ks   = sm + OFF_KS;
    float* Vs   = sm + OFF_X;
    float* ctx  = sm + OFF_X;
    float* kcs  = sm + OFF_KCS;
    float* diag = sm + OFF_DIAG;
    float* hm   = sm + OFF_HM;
    float* hd   = sm + OFF_HD;

    const int tid = threadIdx.x;
    const int w   = tid >> 5;
    const int c   = tid & 31;
    const int bh  = blockIdx.x;
    const int ybase = bh * N_TOK;

    float* og = outg_ + (size_t)bh * N_TOK * D_DIM;

    const unsigned ksAddr  = smem_u32(Ks);
    const unsigned vsAddr  = smem_u32(Vs);
    const unsigned mbK     = smem_u32(sm + OFF_MBAR);       // K/Q barrier
    const unsigned mbV     = mbK + 8;                       // V barrier

    // projection GEMM roles: 8-row group x m-half
    const int nh   = w >> 1;
    const int half = w & 1;
    const int r0   = nh * 8;
    const int mb   = half * 128 + c * 4;

    // ctx GEMM roles: m-half x 8-e group
    const int chalf = w & 1;
    const int e0c   = (w >> 1) * 8;
    const int mbc   = chalf * 128 + c * 4;

    // out GEMM roles: e-half group x (32 row-pairs x 8 e-quads)
    const int gh  = tid >> 8;            // e-half
    const int gt  = tid & 255;
    const int ro  = (gt >> 3) * 2;       // row pair base
    const int eo  = gh * 32 + (gt & 7) * 4;

    // diag roles: row = tid>>3, 8 lanes per row
    const int drow = tid >> 3;
    const int dpos = tid & 7;

    // ---- init barriers, kick off K0 ----
    if (tid == 0) { mbar_init(mbK, 1); mbar_init(mbV, 1); }
    __syncthreads();
    if (tid == 0) {
        mbar_expect_tx(mbK, TILE_BYTES);
        tma_load_2d(ksAddr, &tmK, 0, ybase, mbK);
    }

    // ---- stage Ps = NRM * P, transposed [d][m] (once, LDG) ----
    for (int i = tid; i < M_FEAT * D_DIM / 4; i += THREADS) {
        int m  = i >> 4;
        int d4 = (i & 15) * 4;
        float4 pv = ((const float4*)Pg)[i];
        Ps[(d4 + 0) * PSLD + m] = pv.x * NRM;
        Ps[(d4 + 1) * PSLD + m] = pv.y * NRM;
        Ps[(d4 + 2) * PSLD + m] = pv.z * NRM;
        Ps[(d4 + 3) * PSLD + m] = pv.w * NRM;
    }

    // ---- phase 1: context & kcs ----
    ull cacc2[2][8];
    #pragma unroll
    for (int p = 0; p < 2; p++)
        #pragma unroll
        for (int e = 0; e < 8; e++) cacc2[p][e] = 0ull;
    float kcsr = 0.f;

    for (int t = 0; t < NTILES; t++) {
        __syncthreads();                 // ctx(t-1)/kcs done; Vs free; kp free
        if (tid == 0) {                  // V t, lands under diag+kdash
            mbar_expect_tx(mbV, TILE_BYTES);
            tma_load_2d(vsAddr, &tmV, 0, ybase + t * NT, mbV);
        }
        mbar_wait(mbK, t & 1);           // K t ready

        // diag[n] = (sum k^2)/16 : 8 lanes per row + shfl
        {
            float4 x0 = *(const float4*)&Ks[drow * KSLD + dpos * 8];
            float4 x1 = *(const float4*)&Ks[drow * KSLD + dpos * 8 + 4];
            float s = x0.x*x0.x + x0.y*x0.y + x0.z*x0.z + x0.w*x0.w
                    + x1.x*x1.x + x1.y*x1.y + x1.z*x1.z + x1.w*x1.w;
            s += __shfl_xor_sync(0xffffffffu, s, 1);
            s += __shfl_xor_sync(0xffffffffu, s, 2);
            s += __shfl_xor_sync(0xffffffffu, s, 4);
            if (dpos == 0) diag[drow] = s * DIAGC;
        }
        // kdash GEMM (accumulate)
        ull acc2[8][2];
        #pragma unroll
        for (int i = 0; i < 8; i++) { acc2[i][0] = 0ull; acc2[i][1] = 0ull; }
        for (int dc = 0; dc < D_DIM; dc += 4) {
            float4 a4[8];
            #pragma unroll
            for (int i = 0; i < 8; i++)
                a4[i] = *(const float4*)&Ks[(r0 + i) * KSLD + dc];
            #pragma unroll
            for (int j = 0; j < 4; j++) {
                ulonglong2 bb = *(const ulonglong2*)&Ps[(dc + j) * PSLD + mb];
                #pragma unroll
                for (int i = 0; i < 8; i++) {
                    const float* af = &a4[i].x;
                    ull ad = dup2(af[j]);
                    ffma2(acc2[i][0], ad, bb.x);
                    ffma2(acc2[i][1], ad, bb.y);
                }
            }
        }
        __syncthreads();                 // diag visible; Ks reads done
        if (tid == 0 && t + 1 < NTILES) {       // K t+1 under epilogue+ctx
            mbar_expect_tx(mbK, TILE_BYTES);
            tma_load_2d(ksAddr, &tmK, 0, ybase + (t + 1) * NT, mbK);
        }
        if (tid == 0 && t + 1 == NTILES) {      // Q 0 into Ks (phase 2 prefetch)
            mbar_expect_tx(mbK, TILE_BYTES);
            tma_load_2d(ksAddr, &tmQ, 0, ybase, mbK);
        }
        // kdash epilogue: exp -> kp
        #pragma unroll
        for (int i = 0; i < 8; i++) {
            float dg = diag[r0 + i];
            float2 u0 = unpk(acc2[i][0]);
            float2 u1 = unpk(acc2[i][1]);
            float4 e;
            e.x = __expf(u0.x - dg + EPSF);
            e.y = __expf(u0.y - dg + EPSF);
            e.z = __expf(u1.x - dg + EPSF);
            e.w = __expf(u1.y - dg + EPSF);
            *(float4*)&kp[(r0 + i) * KPLD + mb] = e;
        }
        __syncthreads();                 // kp complete
        if (tid < M_FEAT) {
            float s = 0.f;
            #pragma unroll 8
            for (int n = 0; n < NT; n++) s += kp[n * KPLD + tid];
            kcsr += s;
        }
        mbar_wait(mbV, t & 1);           // V t ready
        // ctx GEMM
        #pragma unroll 4
        for (int n = 0; n < NT; n++) {
            ulonglong2 ka = *(const ulonglong2*)&kp[n * KPLD + mbc];
            float4 v0 = *(const float4*)&Vs[n * KSLD + e0c];
            float4 v1 = *(const float4*)&Vs[n * KSLD + e0c + 4];
            const float vv[8] = {v0.x, v0.y, v0.z, v0.w, v1.x, v1.y, v1.z, v1.w};
            #pragma unroll
            for (int e = 0; e < 8; e++) {
                ull vd = dup2(vv[e]);
                ffma2(cacc2[0][e], ka.x, vd);
                ffma2(cacc2[1][e], ka.y, vd);
            }
        }
    }
    __syncthreads();                     // Vs dead -> write ctx
    {
        #pragma unroll
        for (int p = 0; p < 2; p++) {
            float2 u[8];
            #pragma unroll
            for (int e = 0; e < 8; e++) u[e] = unpk(cacc2[p][e]);
            int m0 = mbc + 2 * p;
            *(float4*)&ctx[m0 * D_DIM + e0c]     = make_float4(u[0].x, u[1].x, u[2].x, u[3].x);
            *(float4*)&ctx[m0 * D_DIM + e0c + 4] = make_float4(u[4].x, u[5].x, u[6].x, u[7].x);
            *(float4*)&ctx[(m0 + 1) * D_DIM + e0c]     = make_float4(u[0].y, u[1].y, u[2].y, u[3].y);
            *(float4*)&ctx[(m0 + 1) * D_DIM + e0c + 4] = make_float4(u[4].y, u[5].y, u[6].y, u[7].y);
        }
        if (tid < M_FEAT) kcs[tid] = kcsr;
    }

    // ---- phase 2: q', D_inv, out ----
    for (int t = 0; t < NTILES; t++) {
        __syncthreads();                 // ctx/kcs visible; out(t-1) done with kp
        mbar_wait(mbK, (NTILES + t) & 1);        // Q t ready

        {   // diag
            float4 x0 = *(const float4*)&Ks[drow * KSLD + dpos * 8];
            float4 x1 = *(const float4*)&Ks[drow * KSLD + dpos * 8 + 4];
            float s = x0.x*x0.x + x0.y*x0.y + x0.z*x0.z + x0.w*x0.w
                    + x1.x*x1.x + x1.y*x1.y + x1.z*x1.z + x1.w*x1.w;
            s += __shfl_xor_sync(0xffffffffu, s, 1);
            s += __shfl_xor_sync(0xffffffffu, s, 2);
            s += __shfl_xor_sync(0xffffffffu, s, 4);
            if (dpos == 0) diag[drow] = s * DIAGC;
        }
        // qdash GEMM (accumulate) + half-max
        ull acc2[8][2];
        #pragma unroll
        for (int i = 0; i < 8; i++) { acc2[i][0] = 0ull; acc2[i][1] = 0ull; }
        for (int dc = 0; dc < D_DIM; dc += 4) {
            float4 a4[8];
            #pragma unroll
            for (int i = 0; i < 8; i++)
                a4[i] = *(const float4*)&Ks[(r0 + i) * KSLD + dc];
            #pragma unroll
            for (int j = 0; j < 4; j++) {
                ulonglong2 bb = *(const ulonglong2*)&Ps[(dc + j) * PSLD + mb];
                #pragma unroll
                for (int i = 0; i < 8; i++) {
                    const float* af = &a4[i].x;
                    ull ad = dup2(af[j]);
                    ffma2(acc2[i][0], ad, bb.x);
                    ffma2(acc2[i][1], ad, bb.y);
                }
            }
        }
        #pragma unroll
        for (int i = 0; i < 8; i++) {
            float2 u0 = unpk(acc2[i][0]);
            float2 u1 = unpk(acc2[i][1]);
            float lm = fmaxf(fmaxf(u0.x, u0.y), fmaxf(u1.x, u1.y));
            #pragma unroll
            for (int off = 16; off; off >>= 1)
                lm = fmaxf(lm, __shfl_xor_sync(0xffffffffu, lm, off));
            if (c == 0) hm[(r0 + i) * 2 + half] = lm;
        }
        __syncthreads();                 // hm + diag visible; Ks reads done
        // stage 2: qpv -> kp, half-denominators
        {
            float4 kc = *(const float4*)&kcs[mb];
            #pragma unroll
            for (int i = 0; i < 8; i++) {
                int r = r0 + i;
                float mx = fmaxf(hm[r * 2], hm[r * 2 + 1]);
                float dg = diag[r];
                float2 u0 = unpk(acc2[i][0]);
                float2 u1 = unpk(acc2[i][1]);
                float4 qv;
                qv.x = __expf(u0.x - dg - mx) + EPSF;
                qv.y = __expf(u0.y - dg - mx) + EPSF;
                qv.z = __expf(u1.x - dg - mx) + EPSF;
                qv.w = __expf(u1.y - dg - mx) + EPSF;
                *(float4*)&kp[r * KPLD + mb] = qv;
                float ds = qv.x * kc.x + qv.y * kc.y + qv.z * kc.z + qv.w * kc.w;
                #pragma unroll
                for (int off = 16; off; off >>= 1)
                    ds += __shfl_xor_sync(0xffffffffu, ds, off);
                if (c == 0) hd[r * 2 + half] = ds;
            }
        }
        __syncthreads();                 // kp + hd complete
        if (tid == 0 && t + 1 < NTILES) {        // Q t+1 under out GEMM
            mbar_expect_tx(mbK, TILE_BYTES);
            tma_load_2d(ksAddr, &tmQ, 0, ybase + (t + 1) * NT, mbK);
        }
        // out GEMM: e-half split, full m reduction, no partial combine
        {
            ull o2[2][2] = {{0ull, 0ull}, {0ull, 0ull}};
            #pragma unroll 2
            for (int mc = 0; mc < M_FEAT; mc += 4) {
                float4 qv0 = *(const float4*)&kp[ro * KPLD + mc];
                float4 qv1 = *(const float4*)&kp[(ro + 1) * KPLD + mc];
                const float* q0 = &qv0.x;
                const float* q1 = &qv1.x;
                #pragma unroll
                for (int j = 0; j < 4; j++) {
                    ulonglong2 cv = *(const ulonglong2*)&ctx[(mc + j) * D_DIM + eo];
                    ull d0 = dup2(q0[j]);
                    ull d1 = dup2(q1[j]);
                    ffma2(o2[0][0], d0, cv.x);
                    ffma2(o2[0][1], d0, cv.y);
                    ffma2(o2[1][0], d1, cv.x);
                    ffma2(o2[1][1], d1, cv.y);
                }
            }
            float s0 = hd[ro * 2] + hd[ro * 2 + 1];
            float s1 = hd[(ro + 1) * 2] + hd[(ro + 1) * 2 + 1];
            float dv0 = __fdividef(1.0f, s0);
            float dv1 = __fdividef(1.0f, s1);
            float2 p00 = unpk(o2[0][0]), p01 = unpk(o2[0][1]);
            float2 p10 = unpk(o2[1][0]), p11 = unpk(o2[1][1]);
            *(float4*)&og[(t * NT + ro) * D_DIM + eo] =
                make_float4(p00.x * dv0, p00.y * dv0, p01.x * dv0, p01.y * dv0);
            *(float4*)&og[(t * NT + ro + 1) * D_DIM + eo] =
                make_float4(p10.x * dv1, p10.y * dv1, p11.x * dv1, p11.y * dv1);
        }
    }
}

// ---------------------------------------------------------------------------
// host side
// ---------------------------------------------------------------------------

typedef CUresult (*tmap_encode_fn)(
    CUtensorMap*, CUtensorMapDataType, cuuint32_t, void*,
    const cuuint64_t*, const cuuint64_t*, const cuuint32_t*, const cuuint32_t*,
    CUtensorMapInterleave, CUtensorMapSwizzle, CUtensorMapL2promotion,
    CUtensorMapFloatOOBfill);

static void make_map(CUtensorMap* tm, tmap_encode_fn enc, const void* base) {
    cuuint64_t dims[2]    = {(cuuint64_t)D_DIM, (cuuint64_t)(N_TOK * BH)};
    cuuint64_t strides[1] = {(cuuint64_t)(D_DIM * 4)};
    cuuint32_t box[2]     = {(cuuint32_t)D_DIM, (cuuint32_t)NT};
    cuuint32_t estr[2]    = {1, 1};
    enc(tm, CU_TENSOR_MAP_DATA_TYPE_FLOAT32, 2, (void*)base,
        dims, strides, box, estr,
        CU_TENSOR_MAP_INTERLEAVE_NONE, CU_TENSOR_MAP_SWIZZLE_NONE,
        CU_TENSOR_MAP_L2_PROMOTION_L2_128B, CU_TENSOR_MAP_FLOAT_OOB_FILL_NONE);
}

extern "C" void kernel_launch(void* const* d_in, const int* in_sizes, int n_in,
                              void* d_out, int out_size)
{
    (void)n_in; (void)out_size; (void)in_sizes;
    const float* P = (const float*)d_in[3];
    float* out = (float*)d_out;

    static tmap_encode_fn enc = nullptr;
    if (!enc) {
        void* fp = nullptr;
        cudaDriverEntryPointQueryResult qr;
        cudaGetDriverEntryPoint("cuTensorMapEncodeTiled", &fp,
                                cudaEnableDefault, &qr);
        enc = (tmap_encode_fn)fp;
    }
    CUtensorMap tmQ, tmK, tmV;
    make_map(&tmQ, enc, d_in[0]);
    make_map(&tmK, enc, d_in[1]);
    make_map(&tmV, enc, d_in[2]);

    static bool attr_set = false;
    if (!attr_set) {
        cudaFuncSetAttribute(fastattn_kernel,
                             cudaFuncAttributeMaxDynamicSharedMemorySize, SMEM_BYTES);
        attr_set = true;
    }
    fastattn_kernel<<<BH, THREADS, SMEM_BYTES>>>(tmQ, tmK, tmV, P, out);
}

// round 9
// speedup vs baseline: 1.1115x; 1.1115x over previous
#include <cuda_runtime.h>
#include <cuda.h>
#include <cstring>

// ---------------------------------------------------------------------------
// Performer (FAVOR+) linear attention, fully fused, fp32 + packed fma.rn.f32x2.
// R8: TMA tile loads; out-GEMM = in-warp split-m (shfl combine, no pbuf);
// kcs accumulated in registers (atomicAdd merge at phase boundary).
// One CTA per (b,h). ratio = m^-0.5 cancels through D_inv and is dropped.
// ---------------------------------------------------------------------------

namespace {
constexpr int N_TOK  = 2048;
constexpr int D_DIM  = 64;
constexpr int M_FEAT = 256;
constexpr int NT     = 64;
constexpr int NTILES = N_TOK / NT;         // 32
constexpr int THREADS = 512;
constexpr int BH     = 128;

constexpr int PSLD = 256;
constexpr int KSLD = 64;                   // TMA-compact K/Q tile
constexpr int KPLD = 260;                  // 16B-aligned, bank-skewed

// smem layout (float offsets)
constexpr int OFF_P    = 0;                         // Ps[64][256]     16384
constexpr int OFF_KP   = OFF_P   + D_DIM * PSLD;    // kp[64][260]     16640
constexpr int OFF_KS   = OFF_KP  + NT * KPLD;       // Ks[64][64]       4096 (TMA dst)
constexpr int OFF_X    = OFF_KS  + NT * KSLD;       // Vs[64][64] | ctx[256][64] 16384
constexpr int OFF_KCS  = OFF_X   + M_FEAT * D_DIM;  // kcs[256]
constexpr int OFF_DIAG = OFF_KCS + M_FEAT;          // diag[64]
constexpr int OFF_HM   = OFF_DIAG + NT;             // hm[64][2]
constexpr int OFF_HD   = OFF_HM + 2 * NT;           // hd[64][2]
constexpr int OFF_MBAR = OFF_HD + 2 * NT;           // 2 mbarriers
constexpr int SMEM_FLOATS = OFF_MBAR + 8;
constexpr int SMEM_BYTES  = SMEM_FLOATS * 4;        // ~216 KB

constexpr int TILE_BYTES = NT * D_DIM * 4;          // 16384

constexpr float NRM   = 0.35355339059327373f;       // 64^-0.25
constexpr float DIAGC = 0.0625f;                    // 0.5 * NRM^2
constexpr float EPSF  = 1e-4f;
}

// ---- packed fp32x2 helpers ----
using ull = unsigned long long;

__device__ __forceinline__ ull dup2(float x) {
    ull r; asm("mov.b64 %0, {%1, %1};" : "=l"(r) : "f"(x)); return r;
}
__device__ __forceinline__ void ffma2(ull& d, ull a, ull b) {
    asm("fma.rn.f32x2 %0, %1, %2, %0;" : "+l"(d) : "l"(a), "l"(b));
}
__device__ __forceinline__ float2 unpk(ull v) {
    float2 f; asm("mov.b64 {%0, %1}, %2;" : "=f"(f.x), "=f"(f.y) : "l"(v)); return f;
}

// ---- TMA / mbarrier helpers ----
__device__ __forceinline__ unsigned smem_u32(const void* p) {
    unsigned a;
    asm("{ .reg .u64 t; cvta.to.shared.u64 t, %1; cvt.u32.u64 %0, t; }"
        : "=r"(a) : "l"(p));
    return a;
}
__device__ __forceinline__ void mbar_init(unsigned mbar, unsigned cnt) {
    asm volatile("mbarrier.init.shared.b64 [%0], %1;" :: "r"(mbar), "r"(cnt) : "memory");
}
__device__ __forceinline__ void mbar_expect_tx(unsigned mbar, unsigned bytes) {
    asm volatile("mbarrier.arrive.expect_tx.shared.b64 _, [%0], %1;"
                 :: "r"(mbar), "r"(bytes) : "memory");
}
__device__ __forceinline__ void mbar_wait(unsigned mbar, unsigned parity) {
    asm volatile(
        "{\n\t.reg .pred P1;\n\t"
        "WL_%=:\n\t"
        "mbarrier.try_wait.parity.acquire.cta.shared::cta.b64 P1, [%0], %1, 0x989680;\n\t"
        "@P1 bra.uni WD_%=;\n\t"
        "bra.uni WL_%=;\n\t"
        "WD_%=:\n\t}"
        :: "r"(mbar), "r"(parity) : "memory");
}
__device__ __forceinline__ void tma_load_2d(unsigned dst, const CUtensorMap* tmap,
                                            int x, int y, unsigned mbar) {
    asm volatile(
        "cp.async.bulk.tensor.2d.shared::cta.global.tile.mbarrier::complete_tx::bytes "
        "[%0], [%1, {%2, %3}], [%4];"
        :: "r"(dst), "l"(tmap), "r"(x), "r"(y), "r"(mbar) : "memory");
}

__global__ __launch_bounds__(THREADS, 1)
void fastattn_kernel(const __grid_constant__ CUtensorMap tmQ,
                     const __grid_constant__ CUtensorMap tmK,
                     const __grid_constant__ CUtensorMap tmV,
                     const float* __restrict__ Pg,
                     float* __restrict__ outg_)
{
    extern __shared__ float sm[];
    float* Ps   = sm + OFF_P;
    float* kp   = sm + OFF_KP;
    float* Ks   = sm + OFF_KS;
    float* Vs   = sm + OFF_X;
    float* ctx  = sm + OFF_X;
    float* kcs  = sm + OFF_KCS;
    float* diag = sm + OFF_DIAG;
    float* hm   = sm + OFF_HM;
    float* hd   = sm + OFF_HD;

    const int tid = threadIdx.x;
    const int w   = tid >> 5;
    const int c   = tid & 31;
    const int bh  = blockIdx.x;
    const int ybase = bh * N_TOK;

    float* og = outg_ + (size_t)bh * N_TOK * D_DIM;

    const unsigned ksAddr  = smem_u32(Ks);
    const unsigned vsAddr  = smem_u32(Vs);
    const unsigned mbK     = smem_u32(sm + OFF_MBAR);
    const unsigned mbV     = mbK + 8;

    // projection GEMM roles: 8-row group x m-half
    const int nh   = w >> 1;
    const int half = w & 1;
    const int r0   = nh * 8;
    const int mb   = half * 128 + c * 4;

    // ctx GEMM roles: m-half x 8-e group
    const int chalf = w & 1;
    const int e0c   = (w >> 1) * 8;
    const int mbc   = chalf * 128 + c * 4;

    // out GEMM roles: warp w -> rows 4w..4w+3; lane: m-half (c>>4) x 4-e (c&15)
    const int ro2 = w * 4;
    const int mh  = c >> 4;
    const int e2  = (c & 15) * 4;
    const int ms  = mh * 128;

    // diag roles
    const int drow = tid >> 3;
    const int dpos = tid & 7;

    // ---- init barriers, zero kcs, kick off K0 ----
    if (tid == 0) { mbar_init(mbK, 1); mbar_init(mbV, 1); }
    if (tid < M_FEAT) kcs[tid] = 0.f;
    __syncthreads();
    if (tid == 0) {
        mbar_expect_tx(mbK, TILE_BYTES);
        tma_load_2d(ksAddr, &tmK, 0, ybase, mbK);
    }

    // ---- stage Ps = NRM * P, transposed [d][m] ----
    for (int i = tid; i < M_FEAT * D_DIM / 4; i += THREADS) {
        int m  = i >> 4;
        int d4 = (i & 15) * 4;
        float4 pv = ((const float4*)Pg)[i];
        Ps[(d4 + 0) * PSLD + m] = pv.x * NRM;
        Ps[(d4 + 1) * PSLD + m] = pv.y * NRM;
        Ps[(d4 + 2) * PSLD + m] = pv.z * NRM;
        Ps[(d4 + 3) * PSLD + m] = pv.w * NRM;
    }

    // ---- phase 1 ----
    ull cacc2[2][8];
    #pragma unroll
    for (int p = 0; p < 2; p++)
        #pragma unroll
        for (int e = 0; e < 8; e++) cacc2[p][e] = 0ull;
    float4 kcsr4 = make_float4(0.f, 0.f, 0.f, 0.f);   // register kcs partials

    for (int t = 0; t < NTILES; t++) {
        __syncthreads();                 // kp/Vs free
        if (tid == 0) {
            mbar_expect_tx(mbV, TILE_BYTES);
            tma_load_2d(vsAddr, &tmV, 0, ybase + t * NT, mbV);
        }
        mbar_wait(mbK, t & 1);

        {   // diag[n] = (sum k^2)/16
            float4 x0 = *(const float4*)&Ks[drow * KSLD + dpos * 8];
            float4 x1 = *(const float4*)&Ks[drow * KSLD + dpos * 8 + 4];
            float s = x0.x*x0.x + x0.y*x0.y + x0.z*x0.z + x0.w*x0.w
                    + x1.x*x1.x + x1.y*x1.y + x1.z*x1.z + x1.w*x1.w;
            s += __shfl_xor_sync(0xffffffffu, s, 1);
            s += __shfl_xor_sync(0xffffffffu, s, 2);
            s += __shfl_xor_sync(0xffffffffu, s, 4);
            if (dpos == 0) diag[drow] = s * DIAGC;
        }
        // kdash GEMM
        ull acc2[8][2];
        #pragma unroll
        for (int i = 0; i < 8; i++) { acc2[i][0] = 0ull; acc2[i][1] = 0ull; }
        for (int dc = 0; dc < D_DIM; dc += 4) {
            float4 a4[8];
            #pragma unroll
            for (int i = 0; i < 8; i++)
                a4[i] = *(const float4*)&Ks[(r0 + i) * KSLD + dc];
            #pragma unroll
            for (int j = 0; j < 4; j++) {
                ulonglong2 bb = *(const ulonglong2*)&Ps[(dc + j) * PSLD + mb];
                #pragma unroll
                for (int i = 0; i < 8; i++) {
                    const float* af = &a4[i].x;
                    ull ad = dup2(af[j]);
                    ffma2(acc2[i][0], ad, bb.x);
                    ffma2(acc2[i][1], ad, bb.y);
                }
            }
        }
        __syncthreads();                 // Ks reads done; diag visible
        if (tid == 0) {                  // next K (or Q0) under epilogue+ctx
            mbar_expect_tx(mbK, TILE_BYTES);
            if (t + 1 < NTILES) tma_load_2d(ksAddr, &tmK, 0, ybase + (t + 1) * NT, mbK);
            else                tma_load_2d(ksAddr, &tmQ, 0, ybase, mbK);
        }
        // epilogue: exp -> kp, accumulate kcs in registers
        #pragma unroll
        for (int i = 0; i < 8; i++) {
            float dg = diag[r0 + i];
            float2 u0 = unpk(acc2[i][0]);
            float2 u1 = unpk(acc2[i][1]);
            float4 e;
            e.x = __expf(u0.x - dg + EPSF);
            e.y = __expf(u0.y - dg + EPSF);
            e.z = __expf(u1.x - dg + EPSF);
            e.w = __expf(u1.y - dg + EPSF);
            *(float4*)&kp[(r0 + i) * KPLD + mb] = e;
            kcsr4.x += e.x; kcsr4.y += e.y; kcsr4.z += e.z; kcsr4.w += e.w;
        }
        __syncthreads();                 // kp complete
        mbar_wait(mbV, t & 1);
        // ctx GEMM
        #pragma unroll 4
        for (int n = 0; n < NT; n++) {
            ulonglong2 ka = *(const ulonglong2*)&kp[n * KPLD + mbc];
            float4 v0 = *(const float4*)&Vs[n * KSLD + e0c];
            float4 v1 = *(const float4*)&Vs[n * KSLD + e0c + 4];
            const float vv[8] = {v0.x, v0.y, v0.z, v0.w, v1.x, v1.y, v1.z, v1.w};
            #pragma unroll
            for (int e = 0; e < 8; e++) {
                ull vd = dup2(vv[e]);
                ffma2(cacc2[0][e], ka.x, vd);
                ffma2(cacc2[1][e], ka.y, vd);
            }
        }
    }
    __syncthreads();                     // Vs dead -> write ctx; merge kcs
    {
        #pragma unroll
        for (int p = 0; p < 2; p++) {
            float2 u[8];
            #pragma unroll
            for (int e = 0; e < 8; e++) u[e] = unpk(cacc2[p][e]);
            int m0 = mbc + 2 * p;
            *(float4*)&ctx[m0 * D_DIM + e0c]     = make_float4(u[0].x, u[1].x, u[2].x, u[3].x);
            *(float4*)&ctx[m0 * D_DIM + e0c + 4] = make_float4(u[4].x, u[5].x, u[6].x, u[7].x);
            *(float4*)&ctx[(m0 + 1) * D_DIM + e0c]     = make_float4(u[0].y, u[1].y, u[2].y, u[3].y);
            *(float4*)&ctx[(m0 + 1) * D_DIM + e0c + 4] = make_float4(u[4].y, u[5].y, u[6].y, u[7].y);
        }
        atomicAdd(&kcs[mb + 0], kcsr4.x);
        atomicAdd(&kcs[mb + 1], kcsr4.y);
        atomicAdd(&kcs[mb + 2], kcsr4.z);
        atomicAdd(&kcs[mb + 3], kcsr4.w);
    }

    // ---- phase 2 ----
    for (int t = 0; t < NTILES; t++) {
        __syncthreads();                 // ctx/kcs visible; out(t-1) done with kp
        mbar_wait(mbK, t & 1);           // Q t (phase NTILES+t, same parity)

        {   // diag
            float4 x0 = *(const float4*)&Ks[drow * KSLD + dpos * 8];
            float4 x1 = *(const float4*)&Ks[drow * KSLD + dpos * 8 + 4];
            float s = x0.x*x0.x + x0.y*x0.y + x0.z*x0.z + x0.w*x0.w
                    + x1.x*x1.x + x1.y*x1.y + x1.z*x1.z + x1.w*x1.w;
            s += __shfl_xor_sync(0xffffffffu, s, 1);
            s += __shfl_xor_sync(0xffffffffu, s, 2);
            s += __shfl_xor_sync(0xffffffffu, s, 4);
            if (dpos == 0) diag[drow] = s * DIAGC;
        }
        // qdash GEMM + half-max
        ull acc2[8][2];
        #pragma unroll
        for (int i = 0; i < 8; i++) { acc2[i][0] = 0ull; acc2[i][1] = 0ull; }
        for (int dc = 0; dc < D_DIM; dc += 4) {
            float4 a4[8];
            #pragma unroll
            for (int i = 0; i < 8; i++)
                a4[i] = *(const float4*)&Ks[(r0 + i) * KSLD + dc];
            #pragma unroll
            for (int j = 0; j < 4; j++) {
                ulonglong2 bb = *(const ulonglong2*)&Ps[(dc + j) * PSLD + mb];
                #pragma unroll
                for (int i = 0; i < 8; i++) {
                    const float* af = &a4[i].x;
                    ull ad = dup2(af[j]);
                    ffma2(acc2[i][0], ad, bb.x);
                    ffma2(acc2[i][1], ad, bb.y);
                }
            }
        }
        #pragma unroll
        for (int i = 0; i < 8; i++) {
            float2 u0 = unpk(acc2[i][0]);
            float2 u1 = unpk(acc2[i][1]);
            float lm = fmaxf(fmaxf(u0.x, u0.y), fmaxf(u1.x, u1.y));
            #pragma unroll
            for (int off = 16; off; off >>= 1)
                lm = fmaxf(lm, __shfl_xor_sync(0xffffffffu, lm, off));
            if (c == 0) hm[(r0 + i) * 2 + half] = lm;
        }
        __syncthreads();                 // hm + diag visible; Ks reads done
        if (tid == 0 && t + 1 < NTILES) {        // Q t+1 under stage2 + out GEMM
            mbar_expect_tx(mbK, TILE_BYTES);
            tma_load_2d(ksAddr, &tmQ, 0, ybase + (t + 1) * NT, mbK);
        }
        // stage 2: qpv -> kp, half-denominators
        {
            float4 kc = *(const float4*)&kcs[mb];
            #pragma unroll
            for (int i = 0; i < 8; i++) {
                int r = r0 + i;
                float mx = fmaxf(hm[r * 2], hm[r * 2 + 1]);
                float dg = diag[r];
                float2 u0 = unpk(acc2[i][0]);
                float2 u1 = unpk(acc2[i][1]);
                float4 qv;
                qv.x = __expf(u0.x - dg - mx) + EPSF;
                qv.y = __expf(u0.y - dg - mx) + EPSF;
                qv.z = __expf(u1.x - dg - mx) + EPSF;
                qv.w = __expf(u1.y - dg - mx) + EPSF;
                *(float4*)&kp[r * KPLD + mb] = qv;
                float ds = qv.x * kc.x + qv.y * kc.y + qv.z * kc.z + qv.w * kc.w;
                #pragma unroll
                for (int off = 16; off; off >>= 1)
                    ds += __shfl_xor_sync(0xffffffffu, ds, off);
                if (c == 0) hd[r * 2 + half] = ds;
            }
        }
        __syncthreads();                 // kp + hd complete
        // out GEMM: in-warp split-m (shfl combine), 4 rows x 4 e per thread
        {
            ull o2[4][2];
            #pragma unroll
            for (int i = 0; i < 4; i++) { o2[i][0] = 0ull; o2[i][1] = 0ull; }
            #pragma unroll 2
            for (int mc = 0; mc < 128; mc += 8) {
                float4 qv[4][2];
                #pragma unroll
                for (int i = 0; i < 4; i++) {
                    qv[i][0] = *(const float4*)&kp[(ro2 + i) * KPLD + ms + mc];
                    qv[i][1] = *(const float4*)&kp[(ro2 + i) * KPLD + ms + mc + 4];
                }
                #pragma unroll
                for (int j = 0; j < 8; j++) {
                    ulonglong2 cv = *(const ulonglong2*)&ctx[(ms + mc + j) * D_DIM + e2];
                    #pragma unroll
                    for (int i = 0; i < 4; i++) {
                        const float* qf = &qv[i][j >> 2].x;
                        ull qd = dup2(qf[j & 3]);
                        ffma2(o2[i][0], qd, cv.x);
                        ffma2(o2[i][1], qd, cv.y);
                    }
                }
            }
            #pragma unroll
            for (int i = 0; i < 4; i++) {
                ull p0 = __shfl_xor_sync(0xffffffffu, o2[i][0], 16);
                ull p1 = __shfl_xor_sync(0xffffffffu, o2[i][1], 16);
                if (mh == 0) {
                    int r = ro2 + i;
                    float dv = __fdividef(1.0f, hd[r * 2] + hd[r * 2 + 1]);
                    float2 a0 = unpk(o2[i][0]), b0 = unpk(p0);
                    float2 a1 = unpk(o2[i][1]), b1 = unpk(p1);
                    *(float4*)&og[(t * NT + r) * D_DIM + e2] =
                        make_float4((a0.x + b0.x) * dv, (a0.y + b0.y) * dv,
                                    (a1.x + b1.x) * dv, (a1.y + b1.y) * dv);
                }
            }
        }
    }
}

// ---------------------------------------------------------------------------
// host side
// ---------------------------------------------------------------------------

typedef CUresult (*tmap_encode_fn)(
    CUtensorMap*, CUtensorMapDataType, cuuint32_t, void*,
    const cuuint64_t*, const cuuint64_t*, const cuuint32_t*, const cuuint32_t*,
    CUtensorMapInterleave, CUtensorMapSwizzle, CUtensorMapL2promotion,
    CUtensorMapFloatOOBfill);

static void make_map(CUtensorMap* tm, tmap_encode_fn enc, const void* base) {
    cuuint64_t dims[2]    = {(cuuint64_t)D_DIM, (cuuint64_t)(N_TOK * BH)};
    cuuint64_t strides[1] = {(cuuint64_t)(D_DIM * 4)};
    cuuint32_t box[2]     = {(cuuint32_t)D_DIM, (cuuint32_t)NT};
    cuuint32_t estr[2]    = {1, 1};
    enc(tm, CU_TENSOR_MAP_DATA_TYPE_FLOAT32, 2, (void*)base,
        dims, strides, box, estr,
        CU_TENSOR_MAP_INTERLEAVE_NONE, CU_TENSOR_MAP_SWIZZLE_NONE,
        CU_TENSOR_MAP_L2_PROMOTION_L2_128B, CU_TENSOR_MAP_FLOAT_OOB_FILL_NONE);
}

extern "C" void kernel_launch(void* const* d_in, const int* in_sizes, int n_in,
                              void* d_out, int out_size)
{
    (void)n_in; (void)out_size; (void)in_sizes;
    const float* P = (const float*)d_in[3];
    float* out = (float*)d_out;

    static tmap_encode_fn enc = nullptr;
    if (!enc) {
        void* fp = nullptr;
        cudaDriverEntryPointQueryResult qr;
        cudaGetDriverEntryPoint("cuTensorMapEncodeTiled", &fp,
                                cudaEnableDefault, &qr);
        enc = (tmap_encode_fn)fp;
    }
    CUtensorMap tmQ, tmK, tmV;
    make_map(&tmQ, enc, d_in[0]);
    make_map(&tmK, enc, d_in[1]);
    make_map(&tmV, enc, d_in[2]);

    static bool attr_set = false;
    if (!attr_set) {
        cudaFuncSetAttribute(fastattn_kernel,
                             cudaFuncAttributeMaxDynamicSharedMemorySize, SMEM_BYTES);
        attr_set = true;
    }
    fastattn_kernel<<<BH, THREADS, SMEM_BYTES>>>(tmQ, tmK, tmV, P, out);
}

// round 14
// speedup vs baseline: 1.4212x; 1.2787x over previous
#include <cuda_runtime.h>
#include <cuda_bf16.h>

namespace {
constexpr int N_TOK = 2048, D_DIM = 64, M_FEAT = 256, NT = 64;
constexpr int NTILES = N_TOK / NT, THREADS = 512, BH = 128;
constexpr int KPLD  = 260;          // kp/qp row stride (f32), 16B-aligned
constexpr int PROWB = 144;          // bf16 row stride (bytes) for Ps / A, ldmatrix-conflict-free

// byte offsets in dynamic smem
constexpr int B_PSHI = 0;                    // Ps_hi bf16 [256][144B]  36864
constexpr int B_PSLO = 36864;                // Ps_lo                   36864
constexpr int B_AHI  = 73728;                // A_hi bf16 [64][144B]     9216
constexpr int B_ALO  = 82944;                // A_lo                     9216
constexpr int B_KP   = 92160;                // kp f32 [64][260]        66560
constexpr int B_CTX  = 158720;               // Vs[64][64] (p1) | ctx[256][64] (p2)  65536
constexpr int B_KCS  = 224256;               // kcs f32 [256]
constexpr int B_DIAG = 225280;               // diag f32 [64]
constexpr int B_HM   = 225536;               // hm f32 [64][4]
constexpr int SMEM_BYTES = 226816;

constexpr float NRM = 0.35355339059327373f, DIAGC = 0.0625f, EPSF = 1e-4f;
}

using ull = unsigned long long;
__device__ __forceinline__ ull dup2(float x){ull r;asm("mov.b64 %0,{%1,%1};":"=l"(r):"f"(x));return r;}
__device__ __forceinline__ void ffma2(ull&d,ull a,ull b){asm("fma.rn.f32x2 %0,%1,%2,%0;":"+l"(d):"l"(a),"l"(b));}
__device__ __forceinline__ float2 unpk(ull v){float2 f;asm("mov.b64 {%0,%1},%2;":"=f"(f.x),"=f"(f.y):"l"(v));return f;}
__device__ __forceinline__ unsigned smem_u32(const void* p){
    unsigned a;asm("{ .reg .u64 t; cvta.to.shared.u64 t, %1; cvt.u32.u64 %0, t; }":"=r"(a):"l"(p));return a;}

__device__ __forceinline__ void ldm4(unsigned* r, unsigned addr){
    asm volatile("ldmatrix.sync.aligned.m8n8.x4.shared.b16 {%0,%1,%2,%3}, [%4];"
        : "=r"(r[0]),"=r"(r[1]),"=r"(r[2]),"=r"(r[3]) : "r"(addr));
}
__device__ __forceinline__ void mma16816(float* c, const unsigned* a, unsigned b0, unsigned b1){
    asm volatile("mma.sync.aligned.m16n8k16.row.col.f32.bf16.bf16.f32 "
        "{%0,%1,%2,%3},{%4,%5,%6,%7},{%8,%9},{%0,%1,%2,%3};"
        : "+f"(c[0]),"+f"(c[1]),"+f"(c[2]),"+f"(c[3])
        : "r"(a[0]),"r"(a[1]),"r"(a[2]),"r"(a[3]),"r"(b0),"r"(b1));
}
// write a bf16 (hi,lo) split pair (x0,x1) at byte offset off in both arrays
__device__ __forceinline__ void split_sts(char* hi, char* lo, unsigned off, float x0, float x1){
    __nv_bfloat16 h0 = __float2bfloat16_rn(x0), h1 = __float2bfloat16_rn(x1);
    __nv_bfloat16 l0 = __float2bfloat16_rn(x0 - __bfloat162float(h0));
    __nv_bfloat16 l1 = __float2bfloat16_rn(x1 - __bfloat162float(h1));
    *(unsigned*)(hi+off) = (unsigned)__bfloat16_as_ushort(h0) | ((unsigned)__bfloat16_as_ushort(h1)<<16);
    *(unsigned*)(lo+off) = (unsigned)__bfloat16_as_ushort(l0) | ((unsigned)__bfloat16_as_ushort(l1)<<16);
}

__global__ __launch_bounds__(THREADS, 1)
void fastattn_kernel(const float* __restrict__ qg_, const float* __restrict__ kg_,
                     const float* __restrict__ vg_, const float* __restrict__ Pg,
                     float* __restrict__ outg_)
{
    extern __shared__ char smb[];
    float* kpf  = (float*)(smb + B_KP);
    float* Vs   = (float*)(smb + B_CTX);
    float* ctxf = (float*)(smb + B_CTX);
    float* kcsf = (float*)(smb + B_KCS);
    float* diag = (float*)(smb + B_DIAG);
    float* hmf  = (float*)(smb + B_HM);

    const int tid = threadIdx.x, w = tid >> 5, c = tid & 31, bh = blockIdx.x;
    const float* qg = qg_ + (size_t)bh * N_TOK * D_DIM;
    const float* kg = kg_ + (size_t)bh * N_TOK * D_DIM;
    const float* vg = vg_ + (size_t)bh * N_TOK * D_DIM;
    float*       og = outg_ + (size_t)bh * N_TOK * D_DIM;

    // MMA roles: warp = 16-row group (w>>2) x 64-col block (w&3)
    const int r0  = (w >> 2) * 16;
    const int mb4 = w & 3;
    const int n0b = mb4 * 64;
    // per-lane ldmatrix offsets
    const int arow = r0 + (c & 7) + ((c >> 3) & 1) * 8;      // A: mats rows lo/lo+8, k lo/hi
    const int akof = (c >> 4) * 8;
    const int brow = (c & 7) + ((c >> 4) & 1) * 8;            // B: mats n lo/hi, k lo/hi
    const int bkof = ((c >> 3) & 1) * 8;
    const unsigned aHbase = smem_u32(smb + B_AHI) + arow * PROWB + akof * 2;
    const unsigned aLbase = smem_u32(smb + B_ALO) + arow * PROWB + akof * 2;
    const unsigned bHbase = smem_u32(smb + B_PSHI) + bkof * 2;
    const unsigned bLbase = smem_u32(smb + B_PSLO) + bkof * 2;
    // epilogue rows/cols for C fragments
    const int r_lo = r0 + (c >> 2), r_hi = r_lo + 8;
    const int ccol = (c & 3) * 2;

    // ctx GEMM roles (R9): m-half x 8-e group
    const int chalf = w & 1, e0c = (w >> 1) * 8, mbc = chalf * 128 + c * 4;
    // out GEMM roles (R9): warp -> rows 4w..4w+3; lane: m-half x 4-e
    const int ro2 = w * 4, mh = c >> 4, e2 = (c & 15) * 4, ms = mh * 128;
    // conversion roles: row = tid>>3, seg = tid&7 (8 f32 each)
    const int vrow = tid >> 3, vseg = tid & 7;

    // ---- stage Ps = NRM*P as bf16 hi/lo [m][144B] ----
    {
        int m = tid >> 1, c0 = (tid & 1) * 32;
        const float* pr = Pg + m * D_DIM + c0;
        #pragma unroll
        for (int j = 0; j < 8; j++) {
            float4 p = ((const float4*)pr)[j];
            unsigned off = (unsigned)(m * PROWB + (c0 + j * 4) * 2);
            split_sts(smb+B_PSHI, smb+B_PSLO, off,   p.x*NRM, p.y*NRM);
            split_sts(smb+B_PSHI, smb+B_PSLO, off+4, p.z*NRM, p.w*NRM);
        }
    }

    ull cacc2[2][8];
    #pragma unroll
    for (int p = 0; p < 2; p++)
        #pragma unroll
        for (int e = 0; e < 8; e++) cacc2[p][e] = 0ull;
    float kcsr = 0.f;

    // ================= phase 1 =================
    for (int t = 0; t < NTILES; t++) {
        __syncthreads();                                    // S1: prev tile consumed
        {   // convert K tile -> A hi/lo + diag; stage V
            const float* src = kg + (size_t)(t*NT + vrow) * D_DIM + vseg * 8;
            float4 x0 = ((const float4*)src)[0], x1 = ((const float4*)src)[1];
            float s = x0.x*x0.x + x0.y*x0.y + x0.z*x0.z + x0.w*x0.w
                    + x1.x*x1.x + x1.y*x1.y + x1.z*x1.z + x1.w*x1.w;
            s += __shfl_xor_sync(0xffffffffu, s, 1);
            s += __shfl_xor_sync(0xffffffffu, s, 2);
            s += __shfl_xor_sync(0xffffffffu, s, 4);
            if (vseg == 0) diag[vrow] = s * DIAGC;
            unsigned off = (unsigned)(vrow * PROWB + vseg * 16);
            split_sts(smb+B_AHI, smb+B_ALO, off,    x0.x, x0.y);
            split_sts(smb+B_AHI, smb+B_ALO, off+4,  x0.z, x0.w);
            split_sts(smb+B_AHI, smb+B_ALO, off+8,  x1.x, x1.y);
            split_sts(smb+B_AHI, smb+B_ALO, off+12, x1.z, x1.w);
            #pragma unroll
            for (int r = 0; r < 2; r++) {
                int i = tid + r * THREADS;
                ((float4*)Vs)[i] = ((const float4*)(vg + (size_t)t*NT*D_DIM))[i];
            }
        }
        __syncthreads();                                    // S2: A/Ps/diag/Vs ready
        // kdash GEMM: 3-pass bf16 split mma.sync
        float acc[8][4];
        #pragma unroll
        for (int i = 0; i < 8; i++)
            #pragma unroll
            for (int j = 0; j < 4; j++) acc[i][j] = 0.f;
        #pragma unroll
        for (int ks = 0; ks < 4; ks++) {
            unsigned aH[4], aL[4];
            ldm4(aH, aHbase + ks * 32);
            ldm4(aL, aLbase + ks * 32);
            #pragma unroll
            for (int p = 0; p < 4; p++) {
                unsigned boff = (unsigned)((n0b + p*16 + brow) * PROWB) + ks * 32;
                unsigned bH[4], bL[4];
                ldm4(bH, bHbase + boff);
                ldm4(bL, bLbase + boff);
                mma16816(acc[2*p],   aH, bH[0], bH[1]);
                mma16816(acc[2*p+1], aH, bH[2], bH[3]);
                mma16816(acc[2*p],   aH, bL[0], bL[1]);
                mma16816(acc[2*p+1], aH, bL[2], bL[3]);
                mma16816(acc[2*p],   aL, bH[0], bH[1]);
                mma16816(acc[2*p+1], aL, bH[2], bH[3]);
            }
        }
        {   // epilogue: exp -> kpf
            float dgl = diag[r_lo], dgh = diag[r_hi];
            #pragma unroll
            for (int t8 = 0; t8 < 8; t8++) {
                int col = n0b + t8 * 8 + ccol;
                float2 el = make_float2(__expf(acc[t8][0]-dgl+EPSF), __expf(acc[t8][1]-dgl+EPSF));
                float2 eh = make_float2(__expf(acc[t8][2]-dgh+EPSF), __expf(acc[t8][3]-dgh+EPSF));
                *(float2*)&kpf[r_lo * KPLD + col] = el;
                *(float2*)&kpf[r_hi * KPLD + col] = eh;
            }
        }
        __syncthreads();                                    // S3: kpf ready
        if (tid < M_FEAT) {                                 // kcs partials
            float s = 0.f;
            #pragma unroll 8
            for (int n = 0; n < NT; n++) s += kpf[n * KPLD + tid];
            kcsr += s;
        }
        #pragma unroll 4
        for (int n = 0; n < NT; n++) {                      // ctx GEMM (fp32x2)
            ulonglong2 ka = *(const ulonglong2*)&kpf[n * KPLD + mbc];
            float4 v0 = *(const float4*)&Vs[n * 64 + e0c];
            float4 v1 = *(const float4*)&Vs[n * 64 + e0c + 4];
            const float vv[8] = {v0.x,v0.y,v0.z,v0.w,v1.x,v1.y,v1.z,v1.w};
            #pragma unroll
            for (int e = 0; e < 8; e++) {
                ull vd = dup2(vv[e]);
                ffma2(cacc2[0][e], ka.x, vd);
                ffma2(cacc2[1][e], ka.y, vd);
            }
        }
    }

    // ============ boundary: write ctx + kcs ============
    __syncthreads();                                        // Vs dead
    {
        #pragma unroll
        for (int p = 0; p < 2; p++) {
            float2 u[8];
            #pragma unroll
            for (int e = 0; e < 8; e++) u[e] = unpk(cacc2[p][e]);
            int m0 = mbc + 2 * p;
            *(float4*)&ctxf[m0*64 + e0c]       = make_float4(u[0].x,u[1].x,u[2].x,u[3].x);
            *(float4*)&ctxf[m0*64 + e0c + 4]   = make_float4(u[4].x,u[5].x,u[6].x,u[7].x);
            *(float4*)&ctxf[(m0+1)*64 + e0c]   = make_float4(u[0].y,u[1].y,u[2].y,u[3].y);
            *(float4*)&ctxf[(m0+1)*64 + e0c+4] = make_float4(u[4].y,u[5].y,u[6].y,u[7].y);
        }
        if (tid < M_FEAT) kcsf[tid] = kcsr;
    }

    // ================= phase 2 =================
    for (int t = 0; t < NTILES; t++) {
        __syncthreads();                                    // S1: prev out GEMM done; ctx/kcs visible
        {   // convert Q tile -> A hi/lo + diag
            const float* src = qg + (size_t)(t*NT + vrow) * D_DIM + vseg * 8;
            float4 x0 = ((const float4*)src)[0], x1 = ((const float4*)src)[1];
            float s = x0.x*x0.x + x0.y*x0.y + x0.z*x0.z + x0.w*x0.w
                    + x1.x*x1.x + x1.y*x1.y + x1.z*x1.z + x1.w*x1.w;
            s += __shfl_xor_sync(0xffffffffu, s, 1);
            s += __shfl_xor_sync(0xffffffffu, s, 2);
            s += __shfl_xor_sync(0xffffffffu, s, 4);
            if (vseg == 0) diag[vrow] = s * DIAGC;
            unsigned off = (unsigned)(vrow * PROWB + vseg * 16);
            split_sts(smb+B_AHI, smb+B_ALO, off,    x0.x, x0.y);
            split_sts(smb+B_AHI, smb+B_ALO, off+4,  x0.z, x0.w);
            split_sts(smb+B_AHI, smb+B_ALO, off+8,  x1.x, x1.y);
            split_sts(smb+B_AHI, smb+B_ALO, off+12, x1.z, x1.w);
        }
        __syncthreads();                                    // S2
        float acc[8][4];
        #pragma unroll
        for (int i = 0; i < 8; i++)
            #pragma unroll
            for (int j = 0; j < 4; j++) acc[i][j] = 0.f;
        #pragma unroll
        for (int ks = 0; ks < 4; ks++) {
            unsigned aH[4], aL[4];
            ldm4(aH, aHbase + ks * 32);
            ldm4(aL, aLbase + ks * 32);
            #pragma unroll
            for (int p = 0; p < 4; p++) {
                unsigned boff = (unsigned)((n0b + p*16 + brow) * PROWB) + ks * 32;
                unsigned bH[4], bL[4];
                ldm4(bH, bHbase + boff);
                ldm4(bL, bLbase + boff);
                mma16816(acc[2*p],   aH, bH[0], bH[1]);
                mma16816(acc[2*p+1], aH, bH[2], bH[3]);
                mma16816(acc[2*p],   aH, bL[0], bL[1]);
                mma16816(acc[2*p+1], aH, bL[2], bL[3]);
                mma16816(acc[2*p],   aL, bH[0], bH[1]);
                mma16816(acc[2*p+1], aL, bH[2], bH[3]);
            }
        }
        {   // partial row-max over this warp's 64 cols
            float ml = -1e30f, mh2 = -1e30f;
            #pragma unroll
            for (int t8 = 0; t8 < 8; t8++) {
                ml  = fmaxf(ml,  fmaxf(acc[t8][0], acc[t8][1]));
                mh2 = fmaxf(mh2, fmaxf(acc[t8][2], acc[t8][3]));
            }
            ml  = fmaxf(ml,  __shfl_xor_sync(0xffffffffu, ml, 1));
            ml  = fmaxf(ml,  __shfl_xor_sync(0xffffffffu, ml, 2));
            mh2 = fmaxf(mh2, __shfl_xor_sync(0xffffffffu, mh2, 1));
            mh2 = fmaxf(mh2, __shfl_xor_sync(0xffffffffu, mh2, 2));
            if ((c & 3) == 0) { hmf[r_lo*4 + mb4] = ml; hmf[r_hi*4 + mb4] = mh2; }
        }
        __syncthreads();                                    // S3: hm ready
        {   // exp with full-row max -> kpf (q')
            float4 hl = *(const float4*)&hmf[r_lo*4];
            float4 hh = *(const float4*)&hmf[r_hi*4];
            float mxl = fmaxf(fmaxf(hl.x,hl.y), fmaxf(hl.z,hl.w));
            float mxh = fmaxf(fmaxf(hh.x,hh.y), fmaxf(hh.z,hh.w));
            float dgl = diag[r_lo] + mxl, dgh = diag[r_hi] + mxh;
            #pragma unroll
            for (int t8 = 0; t8 < 8; t8++) {
                int col = n0b + t8 * 8 + ccol;
                float2 el = make_float2(__expf(acc[t8][0]-dgl)+EPSF, __expf(acc[t8][1]-dgl)+EPSF);
                float2 eh = make_float2(__expf(acc[t8][2]-dgh)+EPSF, __expf(acc[t8][3]-dgh)+EPSF);
                *(float2*)&kpf[r_lo * KPLD + col] = el;
                *(float2*)&kpf[r_hi * KPLD + col] = eh;
            }
        }
        __syncthreads();                                    // S4: kpf (q') ready
        {   // denominators + out GEMM (in-warp split-m, shfl combine)
            float dv[4];
            #pragma unroll
            for (int i = 0; i < 4; i++) {
                const float* qr = kpf + (ro2 + i) * KPLD + c * 8;
                const float* kr = kcsf + c * 8;
                float4 qa = *(const float4*)qr, qb = *(const float4*)(qr + 4);
                float4 ka = *(const float4*)kr, kb = *(const float4*)(kr + 4);
                float ds = qa.x*ka.x + qa.y*ka.y + qa.z*ka.z + qa.w*ka.w
                         + qb.x*kb.x + qb.y*kb.y + qb.z*kb.z + qb.w*kb.w;
                #pragma unroll
                for (int off = 16; off; off >>= 1) ds += __shfl_xor_sync(0xffffffffu, ds, off);
                dv[i] = __fdividef(1.0f, ds);
            }
            ull o2[4][2];
            #pragma unroll
            for (int i = 0; i < 4; i++) { o2[i][0] = 0ull; o2[i][1] = 0ull; }
            #pragma unroll 2
            for (int mc = 0; mc < 128; mc += 8) {
                float4 qv[4][2];
                #pragma unroll
                for (int i = 0; i < 4; i++) {
                    qv[i][0] = *(const float4*)&kpf[(ro2+i)*KPLD + ms + mc];
                    qv[i][1] = *(const float4*)&kpf[(ro2+i)*KPLD + ms + mc + 4];
                }
                #pragma unroll
                for (int j = 0; j < 8; j++) {
                    ulonglong2 cv = *(const ulonglong2*)&ctxf[(ms + mc + j)*64 + e2];
                    #pragma unroll
                    for (int i = 0; i < 4; i++) {
                        const float* qf = &qv[i][j >> 2].x;
                        ull qd = dup2(qf[j & 3]);
                        ffma2(o2[i][0], qd, cv.x);
                        ffma2(o2[i][1], qd, cv.y);
                    }
                }
            }
            #pragma unroll
            for (int i = 0; i < 4; i++) {
                ull p0 = __shfl_xor_sync(0xffffffffu, o2[i][0], 16);
                ull p1 = __shfl_xor_sync(0xffffffffu, o2[i][1], 16);
                if (mh == 0) {
                    float2 a0 = unpk(o2[i][0]), b0 = unpk(p0);
                    float2 a1 = unpk(o2[i][1]), b1 = unpk(p1);
                    float d = dv[i];
                    *(float4*)&og[(t*NT + ro2 + i)*D_DIM + e2] =
                        make_float4((a0.x+b0.x)*d, (a0.y+b0.y)*d, (a1.x+b1.x)*d, (a1.y+b1.y)*d);
                }
            }
        }
    }
}

extern "C" void kernel_launch(void* const* d_in, const int* in_sizes, int n_in,
                              void* d_out, int out_size)
{
    (void)n_in; (void)out_size; (void)in_sizes;
    static bool attr = false;
    if (!attr) {
        cudaFuncSetAttribute(fastattn_kernel, cudaFuncAttributeMaxDynamicSharedMemorySize, SMEM_BYTES);
        attr = true;
    }
    fastattn_kernel<<<BH, THREADS, SMEM_BYTES>>>(
        (const float*)d_in[0], (const float*)d_in[1], (const float*)d_in[2],
        (const float*)d_in[3], (float*)d_out);
}

// round 15
// speedup vs baseline: 1.7899x; 1.2594x over previous
#include <cuda_runtime.h>
#include <cuda_bf16.h>

namespace {
constexpr int N_TOK = 2048, D_DIM = 64, M_FEAT = 256, NT = 64;
constexpr int NTILES = N_TOK / NT, THREADS = 512, BH = 128;
constexpr int KPLD  = 260;          // phase-1 k' f32 row stride (floats)
constexpr int PROWB = 144;          // bf16 row stride (bytes) for Ps / A
constexpr int KROWB = 528;          // bf16 row stride (bytes) for q'/ctx (256 cols + pad)

// byte offsets in dynamic smem
constexpr int B_PSHI = 0;                    // Ps_hi bf16 [256][144]   36864
constexpr int B_PSLO = 36864;                // Ps_lo                   36864
constexpr int B_AHI  = 73728;                // A_hi bf16 [64][144]      9216
constexpr int B_ALO  = 82944;                // A_lo                     9216
constexpr int B_V    = 92160;                // V f32 [64][64] (phase 1) 16384
constexpr int B_CTXH = 92160;                // ctx^T hi bf16 [64][528] (phase 2) 33792
constexpr int B_CTXL = 125952;               // ctx^T lo                33792
constexpr int B_KP   = 159744;               // p1: k' f32 [64][260] 66560 | p2: q' hi bf16 [64][528]
constexpr int B_KPL  = 193536;               // p2: q' lo bf16 [64][528]
constexpr int B_KCS  = 227328;               // kcs f32 [256]
constexpr int B_DIAG = 228352;               // diag f32 [64]
constexpr int B_HM   = 228608;               // hm f32 [64][4]
constexpr int B_HD   = 229632;               // hd f32 [64][4]
constexpr int SMEM_BYTES = 230656;

constexpr float NRM = 0.35355339059327373f, DIAGC = 0.0625f, EPSF = 1e-4f;
}

using ull = unsigned long long;
__device__ __forceinline__ ull dup2(float x){ull r;asm("mov.b64 %0,{%1,%1};":"=l"(r):"f"(x));return r;}
__device__ __forceinline__ void ffma2(ull&d,ull a,ull b){asm("fma.rn.f32x2 %0,%1,%2,%0;":"+l"(d):"l"(a),"l"(b));}
__device__ __forceinline__ float2 unpk(ull v){float2 f;asm("mov.b64 {%0,%1},%2;":"=f"(f.x),"=f"(f.y):"l"(v));return f;}
__device__ __forceinline__ unsigned smem_u32(const void* p){
    unsigned a;asm("{ .reg .u64 t; cvta.to.shared.u64 t, %1; cvt.u32.u64 %0, t; }":"=r"(a):"l"(p));return a;}

__device__ __forceinline__ void ldm4(unsigned* r, unsigned addr){
    asm volatile("ldmatrix.sync.aligned.m8n8.x4.shared.b16 {%0,%1,%2,%3}, [%4];"
        : "=r"(r[0]),"=r"(r[1]),"=r"(r[2]),"=r"(r[3]) : "r"(addr));
}
__device__ __forceinline__ void mma16816(float* c, const unsigned* a, unsigned b0, unsigned b1){
    asm volatile("mma.sync.aligned.m16n8k16.row.col.f32.bf16.bf16.f32 "
        "{%0,%1,%2,%3},{%4,%5,%6,%7},{%8,%9},{%0,%1,%2,%3};"
        : "+f"(c[0]),"+f"(c[1]),"+f"(c[2]),"+f"(c[3])
        : "r"(a[0]),"r"(a[1]),"r"(a[2]),"r"(a[3]),"r"(b0),"r"(b1));
}
__device__ __forceinline__ void split_sts(char* hi, char* lo, unsigned off, float x0, float x1){
    __nv_bfloat16 h0 = __float2bfloat16_rn(x0), h1 = __float2bfloat16_rn(x1);
    __nv_bfloat16 l0 = __float2bfloat16_rn(x0 - __bfloat162float(h0));
    __nv_bfloat16 l1 = __float2bfloat16_rn(x1 - __bfloat162float(h1));
    *(unsigned*)(hi+off) = (unsigned)__bfloat16_as_ushort(h0) | ((unsigned)__bfloat16_as_ushort(h1)<<16);
    *(unsigned*)(lo+off) = (unsigned)__bfloat16_as_ushort(l0) | ((unsigned)__bfloat16_as_ushort(l1)<<16);
}

__global__ __launch_bounds__(THREADS, 1)
void fastattn_kernel(const float* __restrict__ qg_, const float* __restrict__ kg_,
                     const float* __restrict__ vg_, const float* __restrict__ Pg,
                     float* __restrict__ outg_)
{
    extern __shared__ char smb[];
    float* kpf  = (float*)(smb + B_KP);     // phase-1 k' f32
    float* Vs   = (float*)(smb + B_V);      // phase-1 V f32
    float* kcsf = (float*)(smb + B_KCS);
    float* diag = (float*)(smb + B_DIAG);
    float* hmf  = (float*)(smb + B_HM);
    float* hdf  = (float*)(smb + B_HD);

    const int tid = threadIdx.x, w = tid >> 5, c = tid & 31, bh = blockIdx.x;
    const float* qg = qg_ + (size_t)bh * N_TOK * D_DIM;
    const float* kg = kg_ + (size_t)bh * N_TOK * D_DIM;
    const float* vg = vg_ + (size_t)bh * N_TOK * D_DIM;
    float*       og = outg_ + (size_t)bh * N_TOK * D_DIM;

    // projection MMA roles: warp = 16-row group (w>>2) x 64-col block (w&3)
    const int r0  = (w >> 2) * 16;
    const int mb4 = w & 3;
    const int n0b = mb4 * 64;
    const int arow = r0 + (c & 7) + ((c >> 3) & 1) * 8;
    const int akof = (c >> 4) * 8;
    const int brow = (c & 7) + ((c >> 4) & 1) * 8;
    const int bkof = ((c >> 3) & 1) * 8;
    const unsigned aHbase = smem_u32(smb + B_AHI) + arow * PROWB + akof * 2;
    const unsigned aLbase = smem_u32(smb + B_ALO) + arow * PROWB + akof * 2;
    const unsigned bHbase = smem_u32(smb + B_PSHI) + bkof * 2;
    const unsigned bLbase = smem_u32(smb + B_PSLO) + bkof * 2;
    const int r_lo = r0 + (c >> 2), r_hi = r_lo + 8;
    const int ccol = (c & 3) * 2;

    // out MMA roles: warp = token 16-row group (w>>2) x e 16-col block (w&3)
    const int eb   = (w & 3) * 16;
    const unsigned aObase = smem_u32(smb + B_KP)
        + (r0 + (c & 7) + ((c >> 3) & 1) * 8) * KROWB + ((c >> 4) * 8) * 2;
    const unsigned aOLoff = (unsigned)(B_KPL - B_KP);
    const unsigned bObase = smem_u32(smb + B_CTXH)
        + (eb + (c & 7) + ((c >> 4) & 1) * 8) * KROWB + (((c >> 3) & 1) * 8) * 2;
    const unsigned bOLoff = (unsigned)(B_CTXL - B_CTXH);

    // ctx GEMM roles (SIMT): m-half x 8-e group
    const int chalf = w & 1, e0c = (w >> 1) * 8, mbc = chalf * 128 + c * 4;
    // conversion roles
    const int vrow = tid >> 3, vseg = tid & 7;

    // ---- stage Ps = NRM*P as bf16 hi/lo [m][144B] ----
    {
        int m = tid >> 1, c0 = (tid & 1) * 32;
        const float* pr = Pg + m * D_DIM + c0;
        #pragma unroll
        for (int j = 0; j < 8; j++) {
            float4 p = ((const float4*)pr)[j];
            unsigned off = (unsigned)(m * PROWB + (c0 + j * 4) * 2);
            split_sts(smb+B_PSHI, smb+B_PSLO, off,   p.x*NRM, p.y*NRM);
            split_sts(smb+B_PSHI, smb+B_PSLO, off+4, p.z*NRM, p.w*NRM);
        }
    }

    ull cacc2[2][8];
    #pragma unroll
    for (int p = 0; p < 2; p++)
        #pragma unroll
        for (int e = 0; e < 8; e++) cacc2[p][e] = 0ull;
    float kcsr = 0.f;

    // ================= phase 1 =================
    for (int t = 0; t < NTILES; t++) {
        __syncthreads();                                    // S1
        {   // convert K tile -> A hi/lo + diag; stage V
            const float* src = kg + (size_t)(t*NT + vrow) * D_DIM + vseg * 8;
            float4 x0 = ((const float4*)src)[0], x1 = ((const float4*)src)[1];
            float s = x0.x*x0.x + x0.y*x0.y + x0.z*x0.z + x0.w*x0.w
                    + x1.x*x1.x + x1.y*x1.y + x1.z*x1.z + x1.w*x1.w;
            s += __shfl_xor_sync(0xffffffffu, s, 1);
            s += __shfl_xor_sync(0xffffffffu, s, 2);
            s += __shfl_xor_sync(0xffffffffu, s, 4);
            if (vseg == 0) diag[vrow] = s * DIAGC;
            unsigned off = (unsigned)(vrow * PROWB + vseg * 16);
            split_sts(smb+B_AHI, smb+B_ALO, off,    x0.x, x0.y);
            split_sts(smb+B_AHI, smb+B_ALO, off+4,  x0.z, x0.w);
            split_sts(smb+B_AHI, smb+B_ALO, off+8,  x1.x, x1.y);
            split_sts(smb+B_AHI, smb+B_ALO, off+12, x1.z, x1.w);
            #pragma unroll
            for (int r = 0; r < 2; r++) {
                int i = tid + r * THREADS;
                ((float4*)Vs)[i] = ((const float4*)(vg + (size_t)t*NT*D_DIM))[i];
            }
        }
        __syncthreads();                                    // S2
        float acc[8][4];
        #pragma unroll
        for (int i = 0; i < 8; i++)
            #pragma unroll
            for (int j = 0; j < 4; j++) acc[i][j] = 0.f;
        #pragma unroll
        for (int ks = 0; ks < 4; ks++) {
            unsigned aH[4], aL[4];
            ldm4(aH, aHbase + ks * 32);
            ldm4(aL, aLbase + ks * 32);
            #pragma unroll
            for (int p = 0; p < 4; p++) {
                unsigned boff = (unsigned)((n0b + p*16 + brow) * PROWB) + ks * 32;
                unsigned bH[4], bL[4];
                ldm4(bH, bHbase + boff);
                ldm4(bL, bLbase + boff);
                mma16816(acc[2*p],   aH, bH[0], bH[1]);
                mma16816(acc[2*p+1], aH, bH[2], bH[3]);
                mma16816(acc[2*p],   aH, bL[0], bL[1]);
                mma16816(acc[2*p+1], aH, bL[2], bL[3]);
                mma16816(acc[2*p],   aL, bH[0], bH[1]);
                mma16816(acc[2*p+1], aL, bH[2], bH[3]);
            }
        }
        {   // epilogue: exp -> kpf (f32)
            float dgl = diag[r_lo], dgh = diag[r_hi];
            #pragma unroll
            for (int t8 = 0; t8 < 8; t8++) {
                int col = n0b + t8 * 8 + ccol;
                float2 el = make_float2(__expf(acc[t8][0]-dgl+EPSF), __expf(acc[t8][1]-dgl+EPSF));
                float2 eh = make_float2(__expf(acc[t8][2]-dgh+EPSF), __expf(acc[t8][3]-dgh+EPSF));
                *(float2*)&kpf[r_lo * KPLD + col] = el;
                *(float2*)&kpf[r_hi * KPLD + col] = eh;
            }
        }
        __syncthreads();                                    // S3
        if (tid < M_FEAT) {                                 // kcs partials
            float s = 0.f;
            #pragma unroll 8
            for (int n = 0; n < NT; n++) s += kpf[n * KPLD + tid];
            kcsr += s;
        }
        #pragma unroll 4
        for (int n = 0; n < NT; n++) {                      // ctx GEMM (fp32x2)
            ulonglong2 ka = *(const ulonglong2*)&kpf[n * KPLD + mbc];
            float4 v0 = *(const float4*)&Vs[n * 64 + e0c];
            float4 v1 = *(const float4*)&Vs[n * 64 + e0c + 4];
            const float vv[8] = {v0.x,v0.y,v0.z,v0.w,v1.x,v1.y,v1.z,v1.w};
            #pragma unroll
            for (int e = 0; e < 8; e++) {
                ull vd = dup2(vv[e]);
                ffma2(cacc2[0][e], ka.x, vd);
                ffma2(cacc2[1][e], ka.y, vd);
            }
        }
    }

    // ============ boundary: ctx^T -> bf16 hi/lo [e][m]; kcs ============
    __syncthreads();                                        // Vs dead
    {
        #pragma unroll
        for (int p = 0; p < 2; p++) {
            #pragma unroll
            for (int e = 0; e < 8; e++) {
                float2 u = unpk(cacc2[p][e]);
                unsigned off = (unsigned)((e0c + e) * KROWB + (mbc + 2*p) * 2);
                split_sts(smb+B_CTXH, smb+B_CTXL, off, u.x, u.y);
            }
        }
        if (tid < M_FEAT) kcsf[tid] = kcsr;
    }

    // ================= phase 2 =================
    for (int t = 0; t < NTILES; t++) {
        __syncthreads();                                    // S1: prev out-mma done with KP
        {   // convert Q tile -> A hi/lo + diag
            const float* src = qg + (size_t)(t*NT + vrow) * D_DIM + vseg * 8;
            float4 x0 = ((const float4*)src)[0], x1 = ((const float4*)src)[1];
            float s = x0.x*x0.x + x0.y*x0.y + x0.z*x0.z + x0.w*x0.w
                    + x1.x*x1.x + x1.y*x1.y + x1.z*x1.z + x1.w*x1.w;
            s += __shfl_xor_sync(0xffffffffu, s, 1);
            s += __shfl_xor_sync(0xffffffffu, s, 2);
            s += __shfl_xor_sync(0xffffffffu, s, 4);
            if (vseg == 0) diag[vrow] = s * DIAGC;
            unsigned off = (unsigned)(vrow * PROWB + vseg * 16);
            split_sts(smb+B_AHI, smb+B_ALO, off,    x0.x, x0.y);
            split_sts(smb+B_AHI, smb+B_ALO, off+4,  x0.z, x0.w);
            split_sts(smb+B_AHI, smb+B_ALO, off+8,  x1.x, x1.y);
            split_sts(smb+B_AHI, smb+B_ALO, off+12, x1.z, x1.w);
        }
        __syncthreads();                                    // S2
        float acc[8][4];
        #pragma unroll
        for (int i = 0; i < 8; i++)
            #pragma unroll
            for (int j = 0; j < 4; j++) acc[i][j] = 0.f;
        #pragma unroll
        for (int ks = 0; ks < 4; ks++) {
            unsigned aH[4], aL[4];
            ldm4(aH, aHbase + ks * 32);
            ldm4(aL, aLbase + ks * 32);
            #pragma unroll
            for (int p = 0; p < 4; p++) {
                unsigned boff = (unsigned)((n0b + p*16 + brow) * PROWB) + ks * 32;
                unsigned bH[4], bL[4];
                ldm4(bH, bHbase + boff);
                ldm4(bL, bLbase + boff);
                mma16816(acc[2*p],   aH, bH[0], bH[1]);
                mma16816(acc[2*p+1], aH, bH[2], bH[3]);
                mma16816(acc[2*p],   aH, bL[0], bL[1]);
                mma16816(acc[2*p+1], aH, bL[2], bL[3]);
                mma16816(acc[2*p],   aL, bH[0], bH[1]);
                mma16816(acc[2*p+1], aL, bH[2], bH[3]);
            }
        }
        {   // partial row-max
            float ml = -1e30f, mh2 = -1e30f;
            #pragma unroll
            for (int t8 = 0; t8 < 8; t8++) {
                ml  = fmaxf(ml,  fmaxf(acc[t8][0], acc[t8][1]));
                mh2 = fmaxf(mh2, fmaxf(acc[t8][2], acc[t8][3]));
            }
            ml  = fmaxf(ml,  __shfl_xor_sync(0xffffffffu, ml, 1));
            ml  = fmaxf(ml,  __shfl_xor_sync(0xffffffffu, ml, 2));
            mh2 = fmaxf(mh2, __shfl_xor_sync(0xffffffffu, mh2, 1));
            mh2 = fmaxf(mh2, __shfl_xor_sync(0xffffffffu, mh2, 2));
            if ((c & 3) == 0) { hmf[r_lo*4 + mb4] = ml; hmf[r_hi*4 + mb4] = mh2; }
        }
        __syncthreads();                                    // S3: hm ready
        {   // exp -> q' bf16 hi/lo; in-register denom partials
            float4 hl = *(const float4*)&hmf[r_lo*4];
            float4 hh = *(const float4*)&hmf[r_hi*4];
            float mxl = fmaxf(fmaxf(hl.x,hl.y), fmaxf(hl.z,hl.w));
            float mxh = fmaxf(fmaxf(hh.x,hh.y), fmaxf(hh.z,hh.w));
            float dgl = diag[r_lo] + mxl, dgh = diag[r_hi] + mxh;
            float dsl = 0.f, dsh = 0.f;
            #pragma unroll
            for (int t8 = 0; t8 < 8; t8++) {
                int col = n0b + t8 * 8 + ccol;
                float q0 = __expf(acc[t8][0]-dgl)+EPSF, q1 = __expf(acc[t8][1]-dgl)+EPSF;
                float q2 = __expf(acc[t8][2]-dgh)+EPSF, q3 = __expf(acc[t8][3]-dgh)+EPSF;
                split_sts(smb+B_KP,  smb+B_KPL, (unsigned)(r_lo * KROWB + col * 2), q0, q1);
                split_sts(smb+B_KP,  smb+B_KPL, (unsigned)(r_hi * KROWB + col * 2), q2, q3);
                float2 kc = *(const float2*)&kcsf[col];
                dsl += q0 * kc.x + q1 * kc.y;
                dsh += q2 * kc.x + q3 * kc.y;
            }
            dsl += __shfl_xor_sync(0xffffffffu, dsl, 1);
            dsl += __shfl_xor_sync(0xffffffffu, dsl, 2);
            dsh += __shfl_xor_sync(0xffffffffu, dsh, 1);
            dsh += __shfl_xor_sync(0xffffffffu, dsh, 2);
            if ((c & 3) == 0) { hdf[r_lo*4 + mb4] = dsl; hdf[r_hi*4 + mb4] = dsh; }
        }
        __syncthreads();                                    // S4: q' bf16 + hd ready
        {   // out-mma: A = q'[n][m], B = ctx^T[e][m], k = m (16 steps), 3-pass
            float oacc[2][4];
            #pragma unroll
            for (int f = 0; f < 2; f++)
                #pragma unroll
                for (int j = 0; j < 4; j++) oacc[f][j] = 0.f;
            #pragma unroll 4
            for (int ks = 0; ks < 16; ks++) {
                unsigned aH[4], aL[4], bH[4], bL[4];
                ldm4(aH, aObase + ks * 32);
                ldm4(aL, aObase + aOLoff + ks * 32);
                ldm4(bH, bObase + ks * 32);
                ldm4(bL, bObase + bOLoff + ks * 32);
                mma16816(oacc[0], aH, bH[0], bH[1]);
                mma16816(oacc[1], aH, bH[2], bH[3]);
                mma16816(oacc[0], aH, bL[0], bL[1]);
                mma16816(oacc[1], aH, bL[2], bL[3]);
                mma16816(oacc[0], aL, bH[0], bH[1]);
                mma16816(oacc[1], aL, bH[2], bH[3]);
            }
            // epilogue: scale by D_inv, store
            float4 h_lo = *(const float4*)&hdf[r_lo*4];
            float4 h_hi = *(const float4*)&hdf[r_hi*4];
            float dvl = __fdividef(1.0f, h_lo.x + h_lo.y + h_lo.z + h_lo.w);
            float dvh = __fdividef(1.0f, h_hi.x + h_hi.y + h_hi.z + h_hi.w);
            #pragma unroll
            for (int f = 0; f < 2; f++) {
                int col = eb + f * 8 + ccol;
                *(float2*)&og[(t*NT + r_lo) * D_DIM + col] =
                    make_float2(oacc[f][0] * dvl, oacc[f][1] * dvl);
                *(float2*)&og[(t*NT + r_hi) * D_DIM + col] =
                    make_float2(oacc[f][2] * dvh, oacc[f][3] * dvh);
            }
        }
    }
}

extern "C" void kernel_launch(void* const* d_in, const int* in_sizes, int n_in,
                              void* d_out, int out_size)
{
    (void)n_in; (void)out_size; (void)in_sizes;
    static bool attr = false;
    if (!attr) {
        cudaFuncSetAttribute(fastattn_kernel, cudaFuncAttributeMaxDynamicSharedMemorySize, SMEM_BYTES);
        attr = true;
    }
    fastattn_kernel<<<BH, THREADS, SMEM_BYTES>>>(
        (const float*)d_in[0], (const float*)d_in[1], (const float*)d_in[2],
        (const float*)d_in[3], (float*)d_out);
}

// round 17
// speedup vs baseline: 2.1218x; 1.1855x over previous
#include <cuda_runtime.h>
#include <cuda_bf16.h>

namespace {
constexpr int N_TOK = 2048, D_DIM = 64, M_FEAT = 256, NT = 64;
constexpr int NTILES = N_TOK / NT, THREADS = 512, BH = 128;
constexpr int PROWB = 144;          // bf16 row stride (bytes): Ps, A, V
constexpr int QROWB = 528;          // bf16 row stride (bytes): k'/q' [n][m], ctx^T [e][m]

// byte offsets in dynamic smem
constexpr int B_PSHI = 0;                    // Ps_hi bf16 [256][144]   36864
constexpr int B_PSLO = 36864;                // Ps_lo                   36864
constexpr int B_AHI  = 73728;                // A_hi bf16 [64][144]      9216
constexpr int B_ALO  = 82944;                // A_lo                     9216
constexpr int B_KPH  = 92160;                // k'/q' hi bf16 [64][528] 33792
constexpr int B_KPL  = 125952;               // k'/q' lo                33792
constexpr int B_VH   = 159744;               // phase1: V hi bf16 [64][144] 9216
constexpr int B_VL   = 168960;               // phase1: V lo                9216
constexpr int B_CTXH = 159744;               // phase2: ctx^T hi [64][528]  33792 (aliases V)
constexpr int B_CTXL = 193536;               // phase2: ctx^T lo            33792
constexpr int B_KCS  = 227328;               // kcs f32 [256]
constexpr int B_DIAG = 228352;               // diag f32 [64]
constexpr int B_HM   = 228608;               // hm f32 [64][4]
constexpr int B_HD   = 229632;               // hd f32 [64][4]
constexpr int SMEM_BYTES = 230656;

constexpr float NRM = 0.35355339059327373f, DIAGC = 0.0625f, EPSF = 1e-4f;
}

__device__ __forceinline__ unsigned smem_u32(const void* p){
    unsigned a;asm("{ .reg .u64 t; cvta.to.shared.u64 t, %1; cvt.u32.u64 %0, t; }":"=r"(a):"l"(p));return a;}

__device__ __forceinline__ void ldm4(unsigned* r, unsigned addr){
    asm volatile("ldmatrix.sync.aligned.m8n8.x4.shared.b16 {%0,%1,%2,%3}, [%4];"
        : "=r"(r[0]),"=r"(r[1]),"=r"(r[2]),"=r"(r[3]) : "r"(addr));
}
__device__ __forceinline__ void ldm4t(unsigned* r, unsigned addr){
    asm volatile("ldmatrix.sync.aligned.m8n8.x4.trans.shared.b16 {%0,%1,%2,%3}, [%4];"
        : "=r"(r[0]),"=r"(r[1]),"=r"(r[2]),"=r"(r[3]) : "r"(addr));
}
__device__ __forceinline__ void mma16816(float* c, const unsigned* a, unsigned b0, unsigned b1){
    asm volatile("mma.sync.aligned.m16n8k16.row.col.f32.bf16.bf16.f32 "
        "{%0,%1,%2,%3},{%4,%5,%6,%7},{%8,%9},{%0,%1,%2,%3};"
        : "+f"(c[0]),"+f"(c[1]),"+f"(c[2]),"+f"(c[3])
        : "r"(a[0]),"r"(a[1]),"r"(a[2]),"r"(a[3]),"r"(b0),"r"(b1));
}
__device__ __forceinline__ void split_sts(char* hi, char* lo, unsigned off, float x0, float x1){
    __nv_bfloat16 h0 = __float2bfloat16_rn(x0), h1 = __float2bfloat16_rn(x1);
    __nv_bfloat16 l0 = __float2bfloat16_rn(x0 - __bfloat162float(h0));
    __nv_bfloat16 l1 = __float2bfloat16_rn(x1 - __bfloat162float(h1));
    *(unsigned*)(hi+off) = (unsigned)__bfloat16_as_ushort(h0) | ((unsigned)__bfloat16_as_ushort(h1)<<16);
    *(unsigned*)(lo+off) = (unsigned)__bfloat16_as_ushort(l0) | ((unsigned)__bfloat16_as_ushort(l1)<<16);
}
__device__ __forceinline__ void split_sts1(char* hi, char* lo, unsigned off, float x){
    __nv_bfloat16 h = __float2bfloat16_rn(x);
    __nv_bfloat16 l = __float2bfloat16_rn(x - __bfloat162float(h));
    *(unsigned short*)(hi+off) = __bfloat16_as_ushort(h);
    *(unsigned short*)(lo+off) = __bfloat16_as_ushort(l);
}

__global__ __launch_bounds__(THREADS, 1)
void fastattn_kernel(const float* __restrict__ qg_, const float* __restrict__ kg_,
                     const float* __restrict__ vg_, const float* __restrict__ Pg,
                     float* __restrict__ outg_)
{
    extern __shared__ char smb[];
    float* kcsf = (float*)(smb + B_KCS);
    float* diag = (float*)(smb + B_DIAG);
    float* hmf  = (float*)(smb + B_HM);
    float* hdf  = (float*)(smb + B_HD);

    const int tid = threadIdx.x, w = tid >> 5, c = tid & 31, bh = blockIdx.x;
    const float* qg = qg_ + (size_t)bh * N_TOK * D_DIM;
    const float* kg = kg_ + (size_t)bh * N_TOK * D_DIM;
    const float* vg = vg_ + (size_t)bh * N_TOK * D_DIM;
    float*       og = outg_ + (size_t)bh * N_TOK * D_DIM;

    // projection MMA roles: warp = 16-row group (w>>2) x 64-col block (w&3)
    const int r0  = (w >> 2) * 16;
    const int mb4 = w & 3;
    const int n0b = mb4 * 64;
    const unsigned aHbase = smem_u32(smb + B_AHI)
        + (r0 + (c & 7) + ((c >> 3) & 1) * 8) * PROWB + ((c >> 4) * 8) * 2;
    const unsigned aLoff = (unsigned)(B_ALO - B_AHI);
    const int brow = (c & 7) + ((c >> 4) & 1) * 8;
    const int bkof = ((c >> 3) & 1) * 8;
    const unsigned bHbase = smem_u32(smb + B_PSHI) + bkof * 2;
    const unsigned bLoff = (unsigned)(B_PSLO - B_PSHI);
    const int r_lo = r0 + (c >> 2), r_hi = r_lo + 8;
    const int ccol = (c & 3) * 2;

    // ctx MMA roles: warp = m 16-group (w), all 64 e.
    // A = ldm.trans on k'[n][m]: lane row=k(n), chunk=m
    const unsigned cAbase = smem_u32(smb + B_KPH)
        + ((c & 7) + ((c >> 4) & 1) * 8) * QROWB + w * 32 + (((c >> 3) & 1) * 16);
    const unsigned cALoff = (unsigned)(B_KPL - B_KPH);
    // B = ldm.trans on V[n][e]: lane row=k(n), chunk=e
    const unsigned cBbase = smem_u32(smb + B_VH)
        + ((c & 7) + ((c >> 3) & 1) * 8) * PROWB + (((c >> 4) & 1) * 16);
    const unsigned cBLoff = (unsigned)(B_VL - B_VH);
    const int m_lo = w * 16 + (c >> 2), m_hi = m_lo + 8;   // ctx C rows

    // out MMA roles (phase 2, R15-proven): warp = token 16-group (w>>2) x e 16-block (w&3)
    const int eb = (w & 3) * 16;
    const unsigned aObase = smem_u32(smb + B_KPH)
        + (r0 + (c & 7) + ((c >> 3) & 1) * 8) * QROWB + ((c >> 4) * 8) * 2;
    const unsigned aOLoff = (unsigned)(B_KPL - B_KPH);
    const unsigned bObase = smem_u32(smb + B_CTXH)
        + (eb + (c & 7) + ((c >> 4) & 1) * 8) * QROWB + (((c >> 3) & 1) * 8) * 2;
    const unsigned bOLoff = (unsigned)(B_CTXL - B_CTXH);

    // conversion roles
    const int vrow = tid >> 3, vseg = tid & 7;

    // ---- stage Ps = NRM*P as bf16 hi/lo; zero kcs ----
    if (tid < M_FEAT) kcsf[tid] = 0.f;
    {
        int m = tid >> 1, c0 = (tid & 1) * 32;
        const float* pr = Pg + m * D_DIM + c0;
        #pragma unroll
        for (int j = 0; j < 8; j++) {
            float4 p = ((const float4*)pr)[j];
            unsigned off = (unsigned)(m * PROWB + (c0 + j * 4) * 2);
            split_sts(smb+B_PSHI, smb+B_PSLO, off,   p.x*NRM, p.y*NRM);
            split_sts(smb+B_PSHI, smb+B_PSLO, off+4, p.z*NRM, p.w*NRM);
        }
    }

    float cacc[8][4];                       // ctx fragments, persistent
    #pragma unroll
    for (int i = 0; i < 8; i++)
        #pragma unroll
        for (int j = 0; j < 4; j++) cacc[i][j] = 0.f;
    float kca[16];                          // kcs register partials
    #pragma unroll
    for (int i = 0; i < 16; i++) kca[i] = 0.f;

    // ================= phase 1 =================
    for (int t = 0; t < NTILES; t++) {
        __syncthreads();                                    // S1
        {   // stage K -> A hi/lo + diag; V -> bf16 hi/lo
            const float* src = kg + (size_t)(t*NT + vrow) * D_DIM + vseg * 8;
            float4 x0 = ((const float4*)src)[0], x1 = ((const float4*)src)[1];
            float s = x0.x*x0.x + x0.y*x0.y + x0.z*x0.z + x0.w*x0.w
                    + x1.x*x1.x + x1.y*x1.y + x1.z*x1.z + x1.w*x1.w;
            s += __shfl_xor_sync(0xffffffffu, s, 1);
            s += __shfl_xor_sync(0xffffffffu, s, 2);
            s += __shfl_xor_sync(0xffffffffu, s, 4);
            if (vseg == 0) diag[vrow] = s * DIAGC;
            unsigned off = (unsigned)(vrow * PROWB + vseg * 16);
            split_sts(smb+B_AHI, smb+B_ALO, off,    x0.x, x0.y);
            split_sts(smb+B_AHI, smb+B_ALO, off+4,  x0.z, x0.w);
            split_sts(smb+B_AHI, smb+B_ALO, off+8,  x1.x, x1.y);
            split_sts(smb+B_AHI, smb+B_ALO, off+12, x1.z, x1.w);
            const float* vs = vg + (size_t)(t*NT + vrow) * D_DIM + vseg * 8;
            float4 v0 = ((const float4*)vs)[0], v1 = ((const float4*)vs)[1];
            split_sts(smb+B_VH, smb+B_VL, off,    v0.x, v0.y);
            split_sts(smb+B_VH, smb+B_VL, off+4,  v0.z, v0.w);
            split_sts(smb+B_VH, smb+B_VL, off+8,  v1.x, v1.y);
            split_sts(smb+B_VH, smb+B_VL, off+12, v1.z, v1.w);
        }
        __syncthreads();                                    // S2
        // kdash MMA (proven)
        float acc[8][4];
        #pragma unroll
        for (int i = 0; i < 8; i++)
            #pragma unroll
            for (int j = 0; j < 4; j++) acc[i][j] = 0.f;
        #pragma unroll
        for (int ks = 0; ks < 4; ks++) {
            unsigned aH[4], aL[4];
            ldm4(aH, aHbase + ks * 32);
            ldm4(aL, aHbase + aLoff + ks * 32);
            #pragma unroll
            for (int p = 0; p < 4; p++) {
                unsigned boff = (unsigned)((n0b + p*16 + brow) * PROWB) + ks * 32;
                unsigned bH[4], bL[4];
                ldm4(bH, bHbase + boff);
                ldm4(bL, bHbase + bLoff + boff);
                mma16816(acc[2*p],   aH, bH[0], bH[1]);
                mma16816(acc[2*p+1], aH, bH[2], bH[3]);
                mma16816(acc[2*p],   aH, bL[0], bL[1]);
                mma16816(acc[2*p+1], aH, bL[2], bL[3]);
                mma16816(acc[2*p],   aL, bH[0], bH[1]);
                mma16816(acc[2*p+1], aL, bH[2], bH[3]);
            }
        }
        {   // epilogue: exp -> k' bf16 hi/lo; kcs register partials
            float dgl = diag[r_lo], dgh = diag[r_hi];
            #pragma unroll
            for (int t8 = 0; t8 < 8; t8++) {
                int col = n0b + t8 * 8 + ccol;
                float q0 = __expf(acc[t8][0]-dgl+EPSF), q1 = __expf(acc[t8][1]-dgl+EPSF);
                float q2 = __expf(acc[t8][2]-dgh+EPSF), q3 = __expf(acc[t8][3]-dgh+EPSF);
                split_sts(smb+B_KPH, smb+B_KPL, (unsigned)(r_lo * QROWB + col * 2), q0, q1);
                split_sts(smb+B_KPH, smb+B_KPL, (unsigned)(r_hi * QROWB + col * 2), q2, q3);
                kca[t8*2+0] += q0 + q2;
                kca[t8*2+1] += q1 + q3;
            }
        }
        __syncthreads();                                    // S3: k' bf16 + V ready
        // ctx MMA: A = k'^T (ldm.trans), B = V^T (ldm.trans), 3-pass, accumulate
        #pragma unroll
        for (int ks = 0; ks < 4; ks++) {
            unsigned aH[4], aL[4];
            ldm4t(aH, cAbase + (ks * 16) * QROWB);
            ldm4t(aL, cAbase + cALoff + (ks * 16) * QROWB);
            #pragma unroll
            for (int p = 0; p < 4; p++) {
                unsigned boff = (unsigned)((ks * 16) * PROWB) + p * 32;
                unsigned bH[4], bL[4];
                ldm4t(bH, cBbase + boff);
                ldm4t(bL, cBbase + cBLoff + boff);
                mma16816(cacc[2*p],   aH, bH[0], bH[1]);
                mma16816(cacc[2*p+1], aH, bH[2], bH[3]);
                mma16816(cacc[2*p],   aH, bL[0], bL[1]);
                mma16816(cacc[2*p+1], aH, bL[2], bL[3]);
                mma16816(cacc[2*p],   aL, bH[0], bH[1]);
                mma16816(cacc[2*p+1], aL, bH[2], bH[3]);
            }
        }
    }

    // ============ boundary: kcs merge; ctx -> ctx^T bf16 hi/lo [e][m] ============
    {   // kcs: reduce over lanes sharing a column, then atomic merge
        #pragma unroll
        for (int i = 0; i < 16; i++) {
            float v = kca[i];
            v += __shfl_xor_sync(0xffffffffu, v, 4);
            v += __shfl_xor_sync(0xffffffffu, v, 8);
            v += __shfl_xor_sync(0xffffffffu, v, 16);
            kca[i] = v;
        }
        if (c < 4) {
            #pragma unroll
            for (int t8 = 0; t8 < 8; t8++) {
                atomicAdd(&kcsf[n0b + t8*8 + ccol + 0], kca[t8*2+0]);
                atomicAdd(&kcsf[n0b + t8*8 + ccol + 1], kca[t8*2+1]);
            }
        }
    }
    __syncthreads();                                        // ctx-mma done everywhere; V dead
    {
        #pragma unroll
        for (int t8 = 0; t8 < 8; t8++) {
            int e0 = t8 * 8 + ccol;
            split_sts1(smb+B_CTXH, smb+B_CTXL, (unsigned)(e0 * QROWB + m_lo * 2),       cacc[t8][0]);
            split_sts1(smb+B_CTXH, smb+B_CTXL, (unsigned)((e0+1) * QROWB + m_lo * 2),   cacc[t8][1]);
            split_sts1(smb+B_CTXH, smb+B_CTXL, (unsigned)(e0 * QROWB + m_hi * 2),       cacc[t8][2]);
            split_sts1(smb+B_CTXH, smb+B_CTXL, (unsigned)((e0+1) * QROWB + m_hi * 2),   cacc[t8][3]);
        }
    }

    // ================= phase 2 (R15-proven, rebased) =================
    for (int t = 0; t < NTILES; t++) {
        __syncthreads();                                    // S1: prev out-mma done; ctx/kcs ready
        {   // stage Q -> A hi/lo + diag
            const float* src = qg + (size_t)(t*NT + vrow) * D_DIM + vseg * 8;
            float4 x0 = ((const float4*)src)[0], x1 = ((const float4*)src)[1];
            float s = x0.x*x0.x + x0.y*x0.y + x0.z*x0.z + x0.w*x0.w
                    + x1.x*x1.x + x1.y*x1.y + x1.z*x1.z + x1.w*x1.w;
            s += __shfl_xor_sync(0xffffffffu, s, 1);
            s += __shfl_xor_sync(0xffffffffu, s, 2);
            s += __shfl_xor_sync(0xffffffffu, s, 4);
            if (vseg == 0) diag[vrow] = s * DIAGC;
            unsigned off = (unsigned)(vrow * PROWB + vseg * 16);
            split_sts(smb+B_AHI, smb+B_ALO, off,    x0.x, x0.y);
            split_sts(smb+B_AHI, smb+B_ALO, off+4,  x0.z, x0.w);
            split_sts(smb+B_AHI, smb+B_ALO, off+8,  x1.x, x1.y);
            split_sts(smb+B_AHI, smb+B_ALO, off+12, x1.z, x1.w);
        }
        __syncthreads();                                    // S2
        float acc[8][4];
        #pragma unroll
        for (int i = 0; i < 8; i++)
            #pragma unroll
            for (int j = 0; j < 4; j++) acc[i][j] = 0.f;
        #pragma unroll
        for (int ks = 0; ks < 4; ks++) {
            unsigned aH[4], aL[4];
            ldm4(aH, aHbase + ks * 32);
            ldm4(aL, aHbase + aLoff + ks * 32);
            #pragma unroll
            for (int p = 0; p < 4; p++) {
                unsigned boff = (unsigned)((n0b + p*16 + brow) * PROWB) + ks * 32;
                unsigned bH[4], bL[4];
                ldm4(bH, bHbase + boff);
                ldm4(bL, bHbase + bLoff + boff);
                mma16816(acc[2*p],   aH, bH[0], bH[1]);
                mma16816(acc[2*p+1], aH, bH[2], bH[3]);
                mma16816(acc[2*p],   aH, bL[0], bL[1]);
                mma16816(acc[2*p+1], aH, bL[2], bL[3]);
                mma16816(acc[2*p],   aL, bH[0], bH[1]);
                mma16816(acc[2*p+1], aL, bH[2], bH[3]);
            }
        }
        {   // partial row-max
            float ml = -1e30f, mh2 = -1e30f;
            #pragma unroll
            for (int t8 = 0; t8 < 8; t8++) {
                ml  = fmaxf(ml,  fmaxf(acc[t8][0], acc[t8][1]));
                mh2 = fmaxf(mh2, fmaxf(acc[t8][2], acc[t8][3]));
            }
            ml  = fmaxf(ml,  __shfl_xor_sync(0xffffffffu, ml, 1));
            ml  = fmaxf(ml,  __shfl_xor_sync(0xffffffffu, ml, 2));
            mh2 = fmaxf(mh2, __shfl_xor_sync(0xffffffffu, mh2, 1));
            mh2 = fmaxf(mh2, __shfl_xor_sync(0xffffffffu, mh2, 2));
            if ((c & 3) == 0) { hmf[r_lo*4 + mb4] = ml; hmf[r_hi*4 + mb4] = mh2; }
        }
        __syncthreads();                                    // S3: hm ready
        {   // exp -> q' bf16 hi/lo; in-register denominator partials
            float4 hl = *(const float4*)&hmf[r_lo*4];
            float4 hh = *(const float4*)&hmf[r_hi*4];
            float mxl = fmaxf(fmaxf(hl.x,hl.y), fmaxf(hl.z,hl.w));
            float mxh = fmaxf(fmaxf(hh.x,hh.y), fmaxf(hh.z,hh.w));
            float dgl = diag[r_lo] + mxl, dgh = diag[r_hi] + mxh;
            float dsl = 0.f, dsh = 0.f;
            #pragma unroll
            for (int t8 = 0; t8 < 8; t8++) {
                int col = n0b + t8 * 8 + ccol;
                float q0 = __expf(acc[t8][0]-dgl)+EPSF, q1 = __expf(acc[t8][1]-dgl)+EPSF;
                float q2 = __expf(acc[t8][2]-dgh)+EPSF, q3 = __expf(acc[t8][3]-dgh)+EPSF;
                split_sts(smb+B_KPH, smb+B_KPL, (unsigned)(r_lo * QROWB + col * 2), q0, q1);
                split_sts(smb+B_KPH, smb+B_KPL, (unsigned)(r_hi * QROWB + col * 2), q2, q3);
                float2 kc = *(const float2*)&kcsf[col];
                dsl += q0 * kc.x + q1 * kc.y;
                dsh += q2 * kc.x + q3 * kc.y;
            }
            dsl += __shfl_xor_sync(0xffffffffu, dsl, 1);
            dsl += __shfl_xor_sync(0xffffffffu, dsl, 2);
            dsh += __shfl_xor_sync(0xffffffffu, dsh, 1);
            dsh += __shfl_xor_sync(0xffffffffu, dsh, 2);
            if ((c & 3) == 0) { hdf[r_lo*4 + mb4] = dsl; hdf[r_hi*4 + mb4] = dsh; }
        }
        __syncthreads();                                    // S4: q' bf16 + hd ready
        {   // out-mma: A = q'[n][m], B = ctx^T[e][m], 16 k-steps, 3-pass
            float oacc[2][4];
            #pragma unroll
            for (int f = 0; f < 2; f++)
                #pragma unroll
                for (int j = 0; j < 4; j++) oacc[f][j] = 0.f;
            #pragma unroll 4
            for (int ks = 0; ks < 16; ks++) {
                unsigned aH[4], aL[4], bH[4], bL[4];
                ldm4(aH, aObase + ks * 32);
                ldm4(aL, aObase + aOLoff + ks * 32);
                ldm4(bH, bObase + ks * 32);
                ldm4(bL, bObase + bOLoff + ks * 32);
                mma16816(oacc[0], aH, bH[0], bH[1]);
                mma16816(oacc[1], aH, bH[2], bH[3]);
                mma16816(oacc[0], aH, bL[0], bL[1]);
                mma16816(oacc[1], aH, bL[2], bL[3]);
                mma16816(oacc[0], aL, bH[0], bH[1]);
                mma16816(oacc[1], aL, bH[2], bH[3]);
            }
            float4 h_lo = *(const float4*)&hdf[r_lo*4];
            float4 h_hi = *(const float4*)&hdf[r_hi*4];
            float dvl = __fdividef(1.0f, h_lo.x + h_lo.y + h_lo.z + h_lo.w);
            float dvh = __fdividef(1.0f, h_hi.x + h_hi.y + h_hi.z + h_hi.w);
            #pragma unroll
            for (int f = 0; f < 2; f++) {
                int col = eb + f * 8 + ccol;
                *(float2*)&og[(t*NT + r_lo) * D_DIM + col] =
                    make_float2(oacc[f][0] * dvl, oacc[f][1] * dvl);
                *(float2*)&og[(t*NT + r_hi) * D_DIM + col] =
                    make_float2(oacc[f][2] * dvh, oacc[f][3] * dvh);
            }
        }
    }
}

extern "C" void kernel_launch(void* const* d_in, const int* in_sizes, int n_in,
                              void* d_out, int out_size)
{
    (void)n_in; (void)out_size; (void)in_sizes;
    static bool attr = false;
    if (!attr) {
        cudaFuncSetAttribute(fastattn_kernel, cudaFuncAttributeMaxDynamicSharedMemorySize, SMEM_BYTES);
        attr = true;
    }
    fastattn_kernel<<<BH, THREADS, SMEM_BYTES>>>(
        (const float*)d_in[0], (const float*)d_in[1], (const float*)d_in[2],
        (const float*)d_in[3], (float*)d_out);
}